// round 7
// baseline (speedup 1.0000x reference)
#include <cuda_runtime.h>
#include <cuda_bf16.h>
#include <cstdint>
#include <cstddef>

#define NN 50000
#define EMAX 800000

// ---------------- scratch (device globals; no allocation allowed) ----------------
__device__ float g_xh[(size_t)NN * 256];
__device__ float g_agg[(size_t)NN * 256];
__device__ float g_ssrc[NN * 4];
__device__ float g_sdst[NN * 4];
__device__ unsigned g_smax[4];
__device__ int   g_off[NN + 1];
__device__ int   g_deg[NN];
__device__ int   g_cur[NN];
__device__ int   g_adj[EMAX];

// split bf16 buffers
__device__ __align__(16) __nv_bfloat16 g_Phi[(size_t)NN * 256];
__device__ __align__(16) __nv_bfloat16 g_Plo[(size_t)NN * 256];
__device__ __align__(16) __nv_bfloat16 g_Qhi[(size_t)NN * 256];
__device__ __align__(16) __nv_bfloat16 g_Qlo[(size_t)NN * 256];
__device__ __align__(16) __nv_bfloat16 g_whi[131072];
__device__ __align__(16) __nv_bfloat16 g_wlo[131072];
// weight offsets: w1:0 (32768), w2:32768 (16384), g1:49152 (32768), g2:81920 (32768), g3:114688 (4096)

__device__ __forceinline__ float lrelu(float x) { return fmaxf(x, 0.2f * x); }
__device__ __forceinline__ float elu1(float x)  { return x > 0.f ? x : expm1f(x); }
__device__ __forceinline__ unsigned fenc(float f) {
    unsigned u = __float_as_uint(f);
    return (u & 0x80000000u) ? ~u : (u | 0x80000000u);
}
__device__ __forceinline__ float fdec(unsigned u) {
    return (u & 0x80000000u) ? __uint_as_float(u ^ 0x80000000u) : __uint_as_float(~u);
}

// ---------------- CSR build ----------------
__global__ void deg_kernel(const int* __restrict__ dst, int E) {
    int i = blockIdx.x * blockDim.x + threadIdx.x;
    if (i < E) atomicAdd(&g_deg[dst[i]], 1);
}

__global__ void scan_kernel(int n) {
    __shared__ int s[1024];
    int tid = threadIdx.x;
    const int chunk = (n + 1023) / 1024;
    int begin = tid * chunk;
    int endi  = min(begin + chunk, n);
    int sum = 0;
    for (int i = begin; i < endi; i++) sum += g_deg[i];
    s[tid] = sum;
    __syncthreads();
    for (int off = 1; off < 1024; off <<= 1) {
        int v = (tid >= off) ? s[tid - off] : 0;
        __syncthreads();
        s[tid] += v;
        __syncthreads();
    }
    int run = (tid == 0) ? 0 : s[tid - 1];
    for (int i = begin; i < endi; i++) { g_off[i] = run; run += g_deg[i]; }
    if (tid == 1023) g_off[n] = s[1023];
}

__global__ void scatter_kernel(const int* __restrict__ src, const int* __restrict__ dst, int E) {
    int i = blockIdx.x * blockDim.x + threadIdx.x;
    if (i < E) {
        int d = dst[i];
        int pos = g_off[d] + atomicAdd(&g_cur[d], 1);
        g_adj[pos] = src[i];
    }
}

// ---------------- vectorized fp32 -> bf16 hi/lo split (4 elems/thread) ----------------
__global__ void split4_kernel(const float4* __restrict__ a,
                              __nv_bfloat162* __restrict__ hi,
                              __nv_bfloat162* __restrict__ lo, int n4) {
    int i = blockIdx.x * blockDim.x + threadIdx.x;
    if (i < n4) {
        float4 f = a[i];
        __nv_bfloat16 h0 = __float2bfloat16(f.x);
        __nv_bfloat16 h1 = __float2bfloat16(f.y);
        __nv_bfloat16 h2 = __float2bfloat16(f.z);
        __nv_bfloat16 h3 = __float2bfloat16(f.w);
        __nv_bfloat162 a0; a0.x = h0; a0.y = h1;
        __nv_bfloat162 a1; a1.x = h2; a1.y = h3;
        hi[i * 2]     = a0;
        hi[i * 2 + 1] = a1;
        __nv_bfloat162 l0, l1;
        l0.x = __float2bfloat16(f.x - __bfloat162float(h0));
        l0.y = __float2bfloat16(f.y - __bfloat162float(h1));
        l1.x = __float2bfloat16(f.z - __bfloat162float(h2));
        l1.y = __float2bfloat16(f.w - __bfloat162float(h3));
        lo[i * 2]     = l0;
        lo[i * 2 + 1] = l1;
    }
}

__global__ void smax_init_kernel() {
    if (threadIdx.x < 4) g_smax[threadIdx.x] = fenc(-3.0e38f);
}

// ---------------- tensor-core GEMM with split-bf16 operands ----------------
__device__ __forceinline__ uint32_t sptr(const void* p) {
    return (uint32_t)__cvta_generic_to_shared(p);
}
__device__ __forceinline__ void ldsm4(uint32_t* r, uint32_t a) {
    asm volatile("ldmatrix.sync.aligned.m8n8.x4.shared.b16 {%0,%1,%2,%3},[%4];\n"
                 : "=r"(r[0]), "=r"(r[1]), "=r"(r[2]), "=r"(r[3]) : "r"(a));
}
__device__ __forceinline__ void ldsm4t(uint32_t* r, uint32_t a) {
    asm volatile("ldmatrix.sync.aligned.m8n8.x4.trans.shared.b16 {%0,%1,%2,%3},[%4];\n"
                 : "=r"(r[0]), "=r"(r[1]), "=r"(r[2]), "=r"(r[3]) : "r"(a));
}
__device__ __forceinline__ void mma16816(float* d, const uint32_t* a, uint32_t b0, uint32_t b1) {
    asm volatile("mma.sync.aligned.m16n8k16.row.col.f32.bf16.bf16.f32 "
                 "{%0,%1,%2,%3},{%4,%5,%6,%7},{%8,%9},{%0,%1,%2,%3};\n"
                 : "+f"(d[0]), "+f"(d[1]), "+f"(d[2]), "+f"(d[3])
                 : "r"(a[0]), "r"(a[1]), "r"(a[2]), "r"(a[3]), "r"(b0), "r"(b1));
}

#define A_PAD 40
#define B_PAD 136

__global__ __launch_bounds__(256, 2) void tgemm_kernel(
    const __nv_bfloat16* __restrict__ a_hi, const __nv_bfloat16* __restrict__ a_lo,
    const __nv_bfloat16* __restrict__ b_hi, const __nv_bfloat16* __restrict__ b_lo,
    const float* __restrict__ bias,
    float* __restrict__ Cf,
    __nv_bfloat16* __restrict__ c_hi, __nv_bfloat16* __restrict__ c_lo,
    int M, int K, int Nc, int act)
{
    __shared__ __align__(16) __nv_bfloat16 As[2][128 * A_PAD];
    __shared__ __align__(16) __nv_bfloat16 Bs[2][32 * B_PAD];

    const int tid  = threadIdx.x;
    const int wid  = tid >> 5;
    const int lane = tid & 31;
    const int warp_m = (wid & 3) * 32;
    const int warp_n = (wid >> 2) * 64;
    const int bm = blockIdx.y * 128;
    const int bn = blockIdx.x * 128;

    const int id0_row = tid >> 2,          id0_c = tid & 3;
    const int id1_row = (tid + 256) >> 2,  id1_c = tid & 3;
    const int jd0_k   = tid >> 4,          jd0_c = tid & 15;
    const int jd1_k   = (tid + 256) >> 4,  jd1_c = tid & 15;

    const int nst = (3 * K) >> 5;

    {
        const __nv_bfloat16* Ab = a_hi;
        const __nv_bfloat16* Bb = b_hi;
        uint4 z = make_uint4(0, 0, 0, 0);
        uint4 v;
        int gm = bm + id0_row;
        v = (gm < M) ? *(const uint4*)(Ab + (size_t)gm * K + id0_c * 8) : z;
        *(uint4*)(&As[0][id0_row * A_PAD + id0_c * 8]) = v;
        gm = bm + id1_row;
        v = (gm < M) ? *(const uint4*)(Ab + (size_t)gm * K + id1_c * 8) : z;
        *(uint4*)(&As[0][id1_row * A_PAD + id1_c * 8]) = v;
        int gn = bn + jd0_c * 8;
        v = (gn < Nc) ? *(const uint4*)(Bb + (size_t)jd0_k * Nc + gn) : z;
        *(uint4*)(&Bs[0][jd0_k * B_PAD + jd0_c * 8]) = v;
        gn = bn + jd1_c * 8;
        v = (gn < Nc) ? *(const uint4*)(Bb + (size_t)jd1_k * Nc + gn) : z;
        *(uint4*)(&Bs[0][jd1_k * B_PAD + jd1_c * 8]) = v;
    }
    __syncthreads();

    float acc[2][8][4];
#pragma unroll
    for (int mt = 0; mt < 2; mt++)
#pragma unroll
        for (int n8 = 0; n8 < 8; n8++)
#pragma unroll
            for (int r = 0; r < 4; r++) acc[mt][n8][r] = 0.f;

    int buf = 0;
    for (int s = 0; s < nst; s++) {
        const bool pf = (s + 1) < nst;
        uint4 av0, av1, bv0, bv1;
        if (pf) {
            int k0 = (s + 1) * 32;
            int rg = k0 / K;
            int kk = k0 - rg * K;
            const __nv_bfloat16* Ab = (rg == 1) ? a_lo : a_hi;
            const __nv_bfloat16* Bb = (rg == 2) ? b_lo : b_hi;
            uint4 z = make_uint4(0, 0, 0, 0);
            int gm = bm + id0_row;
            av0 = (gm < M) ? *(const uint4*)(Ab + (size_t)gm * K + kk + id0_c * 8) : z;
            gm = bm + id1_row;
            av1 = (gm < M) ? *(const uint4*)(Ab + (size_t)gm * K + kk + id1_c * 8) : z;
            int gn = bn + jd0_c * 8;
            bv0 = (gn < Nc) ? *(const uint4*)(Bb + (size_t)(kk + jd0_k) * Nc + gn) : z;
            gn = bn + jd1_c * 8;
            bv1 = (gn < Nc) ? *(const uint4*)(Bb + (size_t)(kk + jd1_k) * Nc + gn) : z;
        }

        const uint32_t abase = sptr(&As[buf][0]);
        const uint32_t bbase = sptr(&Bs[buf][0]);
#pragma unroll
        for (int h = 0; h < 2; h++) {
            uint32_t afr0[4], afr1[4];
            int arow = warp_m + (lane & 15);
            uint32_t ad0 = abase + (uint32_t)(arow * (A_PAD * 2) + h * 32 + (lane >> 4) * 16);
            uint32_t ad1 = ad0 + 16 * (A_PAD * 2);
            ldsm4(afr0, ad0);
            ldsm4(afr1, ad1);
#pragma unroll
            for (int nt = 0; nt < 4; nt++) {
                uint32_t bfr[4];
                uint32_t bd = bbase
                    + (uint32_t)((h * 16 + (lane & 15)) * (B_PAD * 2)
                    + (warp_n + nt * 16 + ((lane >> 4) << 3)) * 2);
                ldsm4t(bfr, bd);
                mma16816(acc[0][nt * 2],     afr0, bfr[0], bfr[1]);
                mma16816(acc[0][nt * 2 + 1], afr0, bfr[2], bfr[3]);
                mma16816(acc[1][nt * 2],     afr1, bfr[0], bfr[1]);
                mma16816(acc[1][nt * 2 + 1], afr1, bfr[2], bfr[3]);
            }
        }

        if (pf) {
            int nb = buf ^ 1;
            *(uint4*)(&As[nb][id0_row * A_PAD + id0_c * 8]) = av0;
            *(uint4*)(&As[nb][id1_row * A_PAD + id1_c * 8]) = av1;
            *(uint4*)(&Bs[nb][jd0_k * B_PAD + jd0_c * 8]) = bv0;
            *(uint4*)(&Bs[nb][jd1_k * B_PAD + jd1_c * 8]) = bv1;
        }
        __syncthreads();
        buf ^= 1;
    }

#pragma unroll
    for (int mt = 0; mt < 2; mt++) {
#pragma unroll
        for (int n8 = 0; n8 < 8; n8++) {
            int col = bn + warp_n + n8 * 8 + (lane & 3) * 2;
            if (col >= Nc) continue;
            float bb0 = 0.f, bb1 = 0.f;
            if (bias) { bb0 = bias[col]; bb1 = bias[col + 1]; }
            int row0 = bm + warp_m + mt * 16 + (lane >> 2);
            float v0 = acc[mt][n8][0] + bb0;
            float v1 = acc[mt][n8][1] + bb1;
            float v2 = acc[mt][n8][2] + bb0;
            float v3 = acc[mt][n8][3] + bb1;
            if (act) {
                v0 = fmaxf(v0, 0.f); v1 = fmaxf(v1, 0.f);
                v2 = fmaxf(v2, 0.f); v3 = fmaxf(v3, 0.f);
            }
            if (row0 < M) {
                size_t o = (size_t)row0 * Nc + col;
                if (Cf) {
                    float2 p; p.x = v0; p.y = v1;
                    *(float2*)&Cf[o] = p;
                } else {
                    __nv_bfloat16 h0 = __float2bfloat16(v0);
                    __nv_bfloat16 h1 = __float2bfloat16(v1);
                    __nv_bfloat162 hp; hp.x = h0; hp.y = h1;
                    *(__nv_bfloat162*)&c_hi[o] = hp;
                    __nv_bfloat162 lp;
                    lp.x = __float2bfloat16(v0 - __bfloat162float(h0));
                    lp.y = __float2bfloat16(v1 - __bfloat162float(h1));
                    *(__nv_bfloat162*)&c_lo[o] = lp;
                }
            }
            int row1 = row0 + 8;
            if (row1 < M) {
                size_t o = (size_t)row1 * Nc + col;
                if (Cf) {
                    float2 p; p.x = v2; p.y = v3;
                    *(float2*)&Cf[o] = p;
                } else {
                    __nv_bfloat16 h0 = __float2bfloat16(v2);
                    __nv_bfloat16 h1 = __float2bfloat16(v3);
                    __nv_bfloat162 hp; hp.x = h0; hp.y = h1;
                    *(__nv_bfloat162*)&c_hi[o] = hp;
                    __nv_bfloat162 lp;
                    lp.x = __float2bfloat16(v2 - __bfloat162float(h0));
                    lp.y = __float2bfloat16(v3 - __bfloat162float(h1));
                    *(__nv_bfloat162*)&c_lo[o] = lp;
                }
            }
        }
    }
}

// ---------------- attention scores + per-head global max ----------------
__global__ void score_kernel(const float* __restrict__ xh,
                             const float* __restrict__ asrc,
                             const float* __restrict__ adst,
                             float* __restrict__ ssrc, float* __restrict__ sdst, int H)
{
    int w = (blockIdx.x * blockDim.x + threadIdx.x) >> 5;
    int lane = threadIdx.x & 31;
    if (w >= NN * H) return;
    int n = w / H, h = w - n * H;
    int F = H * 64;
    const float* row = xh + (size_t)n * F + h * 64;
    float x0 = row[lane], x1 = row[lane + 32];
    float vs = x0 * asrc[h * 64 + lane] + x1 * asrc[h * 64 + lane + 32];
    float vd = x0 * adst[h * 64 + lane] + x1 * adst[h * 64 + lane + 32];
#pragma unroll
    for (int o = 16; o; o >>= 1) {
        vs += __shfl_xor_sync(0xffffffffu, vs, o);
        vd += __shfl_xor_sync(0xffffffffu, vd, o);
    }
    if (lane == 0) {
        ssrc[w] = vs;
        sdst[w] = vd;
        atomicMax(&g_smax[h], fenc(vs));
    }
}

// ---------------- single-pass segment-softmax aggregation ----------------
// Uses per-head global max bound mb = lrelu(m_h + sd) >= all incoming e (lrelu monotone).
// exp(e - mb) in (0,1]; softmax ratio identical.
__global__ void agg_kernel(const float* __restrict__ xh,
                           const float* __restrict__ ssrc,
                           const float* __restrict__ sdst,
                           float* __restrict__ agg, int H)
{
    int w = (blockIdx.x * blockDim.x + threadIdx.x) >> 5;
    int lane = threadIdx.x & 31;
    if (w >= NN * H) return;
    int n = w / H, h = w - n * H;
    int F = H * 64;
    int start = g_off[n], end = g_off[n + 1];
    float sd = sdst[n * H + h];
    float mb = lrelu(fdec(g_smax[h]) + sd);

    float eself = lrelu(ssrc[n * H + h] + sd);
    float wself = __expf(eself - mb);
    float zpart = (lane == 0) ? wself : 0.f;
    const float* selfrow = xh + (size_t)n * F + h * 64;
    float acc0 = wself * selfrow[lane];
    float acc1 = wself * selfrow[lane + 32];

    for (int j0 = start; j0 < end; j0 += 32) {
        int j = j0 + lane;
        int s = (j < end) ? g_adj[j] : n;
        float wv = 0.f;
        if (j < end) {
            wv = __expf(lrelu(ssrc[s * H + h] + sd) - mb);
            zpart += wv;
        }
        int cnt = min(32, end - j0);
        for (int k = 0; k < cnt; k++) {
            float wk = __shfl_sync(0xffffffffu, wv, k);
            int   sk = __shfl_sync(0xffffffffu, s, k);
            const float* r = xh + (size_t)sk * F + h * 64;
            acc0 = fmaf(wk, r[lane], acc0);
            acc1 = fmaf(wk, r[lane + 32], acc1);
        }
    }
#pragma unroll
    for (int o = 16; o; o >>= 1) zpart += __shfl_xor_sync(0xffffffffu, zpart, o);
    float inv = 1.f / zpart;
    agg[(size_t)n * F + h * 64 + lane]      = acc0 * inv;
    agg[(size_t)n * F + h * 64 + lane + 32] = acc1 * inv;
}

// ---------------- epilogues (vectorized, write split bf16) ----------------
__global__ void bias_elu_split4_kernel(const float4* __restrict__ in, const float* __restrict__ b,
                                       __nv_bfloat162* __restrict__ hi, __nv_bfloat162* __restrict__ lo,
                                       int n4, int Fmask4) {
    int i = blockIdx.x * blockDim.x + threadIdx.x;
    if (i < n4) {
        float4 f = in[i];
        int bidx = (i & Fmask4) * 4;
        float v0 = elu1(f.x + b[bidx]);
        float v1 = elu1(f.y + b[bidx + 1]);
        float v2 = elu1(f.z + b[bidx + 2]);
        float v3 = elu1(f.w + b[bidx + 3]);
        __nv_bfloat16 h0 = __float2bfloat16(v0);
        __nv_bfloat16 h1 = __float2bfloat16(v1);
        __nv_bfloat16 h2 = __float2bfloat16(v2);
        __nv_bfloat16 h3 = __float2bfloat16(v3);
        __nv_bfloat162 a0; a0.x = h0; a0.y = h1;
        __nv_bfloat162 a1; a1.x = h2; a1.y = h3;
        hi[i * 2]     = a0;
        hi[i * 2 + 1] = a1;
        __nv_bfloat162 l0, l1;
        l0.x = __float2bfloat16(v0 - __bfloat162float(h0));
        l0.y = __float2bfloat16(v1 - __bfloat162float(h1));
        l1.x = __float2bfloat16(v2 - __bfloat162float(h2));
        l1.y = __float2bfloat16(v3 - __bfloat162float(h3));
        lo[i * 2]     = l0;
        lo[i * 2 + 1] = l1;
    }
}

__global__ void mean2_bias_elu_split_kernel(const float* __restrict__ in, const float* __restrict__ b,
                                            __nv_bfloat16* __restrict__ hi, __nv_bfloat16* __restrict__ lo,
                                            int total) {
    int i = blockIdx.x * blockDim.x + threadIdx.x;
    if (i < total) {
        int n = i >> 6, d = i & 63;
        float v = 0.5f * (in[(size_t)n * 128 + d] + in[(size_t)n * 128 + 64 + d]) + b[d];
        v = elu1(v);
        __nv_bfloat16 h = __float2bfloat16(v);
        hi[i] = h;
        lo[i] = __float2bfloat16(v - __bfloat162float(h));
    }
}

__global__ void final_bias_kernel(const float* __restrict__ in, const float* __restrict__ b,
                                  float* __restrict__ out, int total) {
    int i = blockIdx.x * blockDim.x + threadIdx.x;
    if (i < total) out[i] = in[i] + b[i & 63];
}

// ---------------- host ----------------
extern "C" void kernel_launch(void* const* d_in, const int* in_sizes, int n_in,
                              void* d_out, int out_size) {
    const float* x     = (const float*)d_in[0];
    const int*   ei    = (const int*)  d_in[1];
    const float* w1    = (const float*)d_in[2];
    const float* b1    = (const float*)d_in[3];
    const float* w2    = (const float*)d_in[4];
    const float* b2    = (const float*)d_in[5];
    const float* g1w   = (const float*)d_in[6];
    const float* g1as  = (const float*)d_in[7];
    const float* g1ad  = (const float*)d_in[8];
    const float* g1b   = (const float*)d_in[9];
    const float* g2w   = (const float*)d_in[10];
    const float* g2as  = (const float*)d_in[11];
    const float* g2ad  = (const float*)d_in[12];
    const float* g2b   = (const float*)d_in[13];
    const float* g3w   = (const float*)d_in[14];
    const float* g3as  = (const float*)d_in[15];
    const float* g3ad  = (const float*)d_in[16];
    const float* g3b   = (const float*)d_in[17];

    int E = in_sizes[1] / 2;
    if (E > EMAX) E = EMAX;
    const int* srcp = ei;
    const int* dstp = ei + E;

    float *xh, *agg, *ssrc, *sdst;
    int *deg, *cur;
    __nv_bfloat16 *Phi, *Plo, *Qhi, *Qlo, *whi, *wlo;
    cudaGetSymbolAddress((void**)&xh,   g_xh);
    cudaGetSymbolAddress((void**)&agg,  g_agg);
    cudaGetSymbolAddress((void**)&ssrc, g_ssrc);
    cudaGetSymbolAddress((void**)&sdst, g_sdst);
    cudaGetSymbolAddress((void**)&deg,  g_deg);
    cudaGetSymbolAddress((void**)&cur,  g_cur);
    cudaGetSymbolAddress((void**)&Phi,  g_Phi);
    cudaGetSymbolAddress((void**)&Plo,  g_Plo);
    cudaGetSymbolAddress((void**)&Qhi,  g_Qhi);
    cudaGetSymbolAddress((void**)&Qlo,  g_Qlo);
    cudaGetSymbolAddress((void**)&whi,  g_whi);
    cudaGetSymbolAddress((void**)&wlo,  g_wlo);

    // weight offsets in whi/wlo
    const int OW1 = 0, OW2 = 32768, OG1 = 49152, OG2 = 81920, OG3 = 114688;

    // ---- CSR build ----
    cudaMemsetAsync(deg, 0, NN * sizeof(int));
    cudaMemsetAsync(cur, 0, NN * sizeof(int));
    deg_kernel<<<(E + 255) / 256, 256>>>(dstp, E);
    scan_kernel<<<1, 1024>>>(NN);
    scatter_kernel<<<(E + 255) / 256, 256>>>(srcp, dstp, E);

    // ---- all splits upfront (x + 5 weights) ----
    {
        int n4 = NN * 256 / 4;
        split4_kernel<<<(n4 + 255) / 256, 256>>>((const float4*)x, (__nv_bfloat162*)Phi, (__nv_bfloat162*)Plo, n4);
        split4_kernel<<<(32768/4 + 255) / 256, 256>>>((const float4*)w1,  (__nv_bfloat162*)(whi + OW1), (__nv_bfloat162*)(wlo + OW1), 32768/4);
        split4_kernel<<<(16384/4 + 255) / 256, 256>>>((const float4*)w2,  (__nv_bfloat162*)(whi + OW2), (__nv_bfloat162*)(wlo + OW2), 16384/4);
        split4_kernel<<<(32768/4 + 255) / 256, 256>>>((const float4*)g1w, (__nv_bfloat162*)(whi + OG1), (__nv_bfloat162*)(wlo + OG1), 32768/4);
        split4_kernel<<<(32768/4 + 255) / 256, 256>>>((const float4*)g2w, (__nv_bfloat162*)(whi + OG2), (__nv_bfloat162*)(wlo + OG2), 32768/4);
        split4_kernel<<<(4096/4 + 255) / 256, 256>>>((const float4*)g3w,  (__nv_bfloat162*)(whi + OG3), (__nv_bfloat162*)(wlo + OG3), 4096/4);
    }

    const int GY = (NN + 127) / 128;   // 391

    // ---- semantic MLP ----
    tgemm_kernel<<<dim3(1, GY), 256>>>(Phi, Plo, whi + OW1, wlo + OW1, b1, nullptr, Qhi, Qlo, NN, 256, 128, 1);
    tgemm_kernel<<<dim3(1, GY), 256>>>(Qhi, Qlo, whi + OW2, wlo + OW2, b2, nullptr, Phi, Plo, NN, 128, 128, 1);

    // ---- GAT 1: 128 -> 4 heads x 64, concat, elu ----
    tgemm_kernel<<<dim3(2, GY), 256>>>(Phi, Plo, whi + OG1, wlo + OG1, nullptr, xh, nullptr, nullptr, NN, 128, 256, 0);
    {
        int W = NN * 4;
        smax_init_kernel<<<1, 32>>>();
        score_kernel<<<(W * 32 + 255) / 256, 256>>>(xh, g1as, g1ad, ssrc, sdst, 4);
        agg_kernel  <<<(W * 32 + 255) / 256, 256>>>(xh, ssrc, sdst, agg, 4);
        int n4 = NN * 256 / 4;
        bias_elu_split4_kernel<<<(n4 + 255) / 256, 256>>>((const float4*)agg, g1b,
            (__nv_bfloat162*)Qhi, (__nv_bfloat162*)Qlo, n4, 63);
    }

    // ---- GAT 2: 256 -> 2 heads x 64, mean, elu ----
    tgemm_kernel<<<dim3(1, GY), 256>>>(Qhi, Qlo, whi + OG2, wlo + OG2, nullptr, xh, nullptr, nullptr, NN, 256, 128, 0);
    {
        int W = NN * 2;
        smax_init_kernel<<<1, 32>>>();
        score_kernel<<<(W * 32 + 255) / 256, 256>>>(xh, g2as, g2ad, ssrc, sdst, 2);
        agg_kernel  <<<(W * 32 + 255) / 256, 256>>>(xh, ssrc, sdst, agg, 2);
        int tot = NN * 64;
        mean2_bias_elu_split_kernel<<<(tot + 1023) / 1024, 1024>>>(agg, g2b, Phi, Plo, tot);
    }

    // ---- GAT 3: 64 -> 1 head x 64 ----
    tgemm_kernel<<<dim3(1, GY), 256>>>(Phi, Plo, whi + OG3, wlo + OG3, nullptr, xh, nullptr, nullptr, NN, 64, 64, 0);
    {
        int W = NN;
        smax_init_kernel<<<1, 32>>>();
        score_kernel<<<(W * 32 + 255) / 256, 256>>>(xh, g3as, g3ad, ssrc, sdst, 1);
        agg_kernel  <<<(W * 32 + 255) / 256, 256>>>(xh, ssrc, sdst, agg, 1);
        int tot = NN * 64;
        final_bias_kernel<<<(tot + 1023) / 1024, 1024>>>(agg, g3b, (float*)d_out, tot);
    }
}

// round 9
// speedup vs baseline: 1.3206x; 1.3206x over previous
#include <cuda_runtime.h>
#include <cuda_bf16.h>
#include <cstdint>
#include <cstddef>

#define NN 50000
#define EMAX 800000

// ---------------- scratch (device globals; no allocation allowed) ----------------
__device__ float g_xh[(size_t)NN * 256];
__device__ float g_agg[(size_t)NN * 256];
__device__ float g_ssrc[NN * 4];
__device__ float g_sdst[NN * 4];
__device__ int   g_off[NN + 1];
__device__ int   g_deg[NN];
__device__ int   g_cur[NN];
__device__ int   g_adj[EMAX];

// split bf16 buffers
__device__ __align__(16) __nv_bfloat16 g_Phi[(size_t)NN * 256];
__device__ __align__(16) __nv_bfloat16 g_Plo[(size_t)NN * 256];
__device__ __align__(16) __nv_bfloat16 g_Qhi[(size_t)NN * 256];
__device__ __align__(16) __nv_bfloat16 g_Qlo[(size_t)NN * 256];
__device__ __align__(16) __nv_bfloat16 g_whi[131072];
__device__ __align__(16) __nv_bfloat16 g_wlo[131072];
// weight offsets: w1:0 (32768), w2:32768 (16384), g1:49152 (32768), g2:81920 (32768), g3:114688 (4096)

__device__ __forceinline__ float lrelu(float x) { return fmaxf(x, 0.2f * x); }
__device__ __forceinline__ float elu1(float x)  { return x > 0.f ? x : expm1f(x); }

// ---------------- CSR build ----------------
__global__ void deg_kernel(const int* __restrict__ dst, int E) {
    int i = blockIdx.x * blockDim.x + threadIdx.x;
    if (i < E) atomicAdd(&g_deg[dst[i]], 1);
}

__global__ void scan_kernel(int n) {
    __shared__ int s[1024];
    int tid = threadIdx.x;
    const int chunk = (n + 1023) / 1024;
    int begin = tid * chunk;
    int endi  = min(begin + chunk, n);
    int sum = 0;
    for (int i = begin; i < endi; i++) sum += g_deg[i];
    s[tid] = sum;
    __syncthreads();
    for (int off = 1; off < 1024; off <<= 1) {
        int v = (tid >= off) ? s[tid - off] : 0;
        __syncthreads();
        s[tid] += v;
        __syncthreads();
    }
    int run = (tid == 0) ? 0 : s[tid - 1];
    for (int i = begin; i < endi; i++) { g_off[i] = run; run += g_deg[i]; }
    if (tid == 1023) g_off[n] = s[1023];
}

__global__ void scatter_kernel(const int* __restrict__ src, const int* __restrict__ dst, int E) {
    int i = blockIdx.x * blockDim.x + threadIdx.x;
    if (i < E) {
        int d = dst[i];
        int pos = g_off[d] + atomicAdd(&g_cur[d], 1);
        g_adj[pos] = src[i];
    }
}

// ---------------- vectorized fp32 -> bf16 hi/lo split (4 elems/thread) ----------------
__global__ void split4_kernel(const float4* __restrict__ a,
                              __nv_bfloat162* __restrict__ hi,
                              __nv_bfloat162* __restrict__ lo, int n4) {
    int i = blockIdx.x * blockDim.x + threadIdx.x;
    if (i < n4) {
        float4 f = a[i];
        __nv_bfloat16 h0 = __float2bfloat16(f.x);
        __nv_bfloat16 h1 = __float2bfloat16(f.y);
        __nv_bfloat16 h2 = __float2bfloat16(f.z);
        __nv_bfloat16 h3 = __float2bfloat16(f.w);
        __nv_bfloat162 a0; a0.x = h0; a0.y = h1;
        __nv_bfloat162 a1; a1.x = h2; a1.y = h3;
        hi[i * 2]     = a0;
        hi[i * 2 + 1] = a1;
        __nv_bfloat162 l0, l1;
        l0.x = __float2bfloat16(f.x - __bfloat162float(h0));
        l0.y = __float2bfloat16(f.y - __bfloat162float(h1));
        l1.x = __float2bfloat16(f.z - __bfloat162float(h2));
        l1.y = __float2bfloat16(f.w - __bfloat162float(h3));
        lo[i * 2]     = l0;
        lo[i * 2 + 1] = l1;
    }
}

// ---------------- tensor-core GEMM with split-bf16 operands ----------------
__device__ __forceinline__ uint32_t sptr(const void* p) {
    return (uint32_t)__cvta_generic_to_shared(p);
}
__device__ __forceinline__ void ldsm4(uint32_t* r, uint32_t a) {
    asm volatile("ldmatrix.sync.aligned.m8n8.x4.shared.b16 {%0,%1,%2,%3},[%4];\n"
                 : "=r"(r[0]), "=r"(r[1]), "=r"(r[2]), "=r"(r[3]) : "r"(a));
}
__device__ __forceinline__ void ldsm4t(uint32_t* r, uint32_t a) {
    asm volatile("ldmatrix.sync.aligned.m8n8.x4.trans.shared.b16 {%0,%1,%2,%3},[%4];\n"
                 : "=r"(r[0]), "=r"(r[1]), "=r"(r[2]), "=r"(r[3]) : "r"(a));
}
__device__ __forceinline__ void mma16816(float* d, const uint32_t* a, uint32_t b0, uint32_t b1) {
    asm volatile("mma.sync.aligned.m16n8k16.row.col.f32.bf16.bf16.f32 "
                 "{%0,%1,%2,%3},{%4,%5,%6,%7},{%8,%9},{%0,%1,%2,%3};\n"
                 : "+f"(d[0]), "+f"(d[1]), "+f"(d[2]), "+f"(d[3])
                 : "r"(a[0]), "r"(a[1]), "r"(a[2]), "r"(a[3]), "r"(b0), "r"(b1));
}

#define A_PAD 40
#define B_PAD 136

__global__ __launch_bounds__(256, 2) void tgemm_kernel(
    const __nv_bfloat16* __restrict__ a_hi, const __nv_bfloat16* __restrict__ a_lo,
    const __nv_bfloat16* __restrict__ b_hi, const __nv_bfloat16* __restrict__ b_lo,
    const float* __restrict__ bias,
    float* __restrict__ Cf,
    __nv_bfloat16* __restrict__ c_hi, __nv_bfloat16* __restrict__ c_lo,
    int M, int K, int Nc, int act)
{
    __shared__ __align__(16) __nv_bfloat16 As[2][128 * A_PAD];
    __shared__ __align__(16) __nv_bfloat16 Bs[2][32 * B_PAD];

    const int tid  = threadIdx.x;
    const int wid  = tid >> 5;
    const int lane = tid & 31;
    const int warp_m = (wid & 3) * 32;
    const int warp_n = (wid >> 2) * 64;
    const int bm = blockIdx.y * 128;
    const int bn = blockIdx.x * 128;

    const int id0_row = tid >> 2,          id0_c = tid & 3;
    const int id1_row = (tid + 256) >> 2,  id1_c = tid & 3;
    const int jd0_k   = tid >> 4,          jd0_c = tid & 15;
    const int jd1_k   = (tid + 256) >> 4,  jd1_c = tid & 15;

    const int nst = (3 * K) >> 5;

    {
        const __nv_bfloat16* Ab = a_hi;
        const __nv_bfloat16* Bb = b_hi;
        uint4 z = make_uint4(0, 0, 0, 0);
        uint4 v;
        int gm = bm + id0_row;
        v = (gm < M) ? *(const uint4*)(Ab + (size_t)gm * K + id0_c * 8) : z;
        *(uint4*)(&As[0][id0_row * A_PAD + id0_c * 8]) = v;
        gm = bm + id1_row;
        v = (gm < M) ? *(const uint4*)(Ab + (size_t)gm * K + id1_c * 8) : z;
        *(uint4*)(&As[0][id1_row * A_PAD + id1_c * 8]) = v;
        int gn = bn + jd0_c * 8;
        v = (gn < Nc) ? *(const uint4*)(Bb + (size_t)jd0_k * Nc + gn) : z;
        *(uint4*)(&Bs[0][jd0_k * B_PAD + jd0_c * 8]) = v;
        gn = bn + jd1_c * 8;
        v = (gn < Nc) ? *(const uint4*)(Bb + (size_t)jd1_k * Nc + gn) : z;
        *(uint4*)(&Bs[0][jd1_k * B_PAD + jd1_c * 8]) = v;
    }
    __syncthreads();

    float acc[2][8][4];
#pragma unroll
    for (int mt = 0; mt < 2; mt++)
#pragma unroll
        for (int n8 = 0; n8 < 8; n8++)
#pragma unroll
            for (int r = 0; r < 4; r++) acc[mt][n8][r] = 0.f;

    int buf = 0;
    for (int s = 0; s < nst; s++) {
        const bool pf = (s + 1) < nst;
        uint4 av0, av1, bv0, bv1;
        if (pf) {
            int k0 = (s + 1) * 32;
            int rg = k0 / K;
            int kk = k0 - rg * K;
            const __nv_bfloat16* Ab = (rg == 1) ? a_lo : a_hi;
            const __nv_bfloat16* Bb = (rg == 2) ? b_lo : b_hi;
            uint4 z = make_uint4(0, 0, 0, 0);
            int gm = bm + id0_row;
            av0 = (gm < M) ? *(const uint4*)(Ab + (size_t)gm * K + kk + id0_c * 8) : z;
            gm = bm + id1_row;
            av1 = (gm < M) ? *(const uint4*)(Ab + (size_t)gm * K + kk + id1_c * 8) : z;
            int gn = bn + jd0_c * 8;
            bv0 = (gn < Nc) ? *(const uint4*)(Bb + (size_t)(kk + jd0_k) * Nc + gn) : z;
            gn = bn + jd1_c * 8;
            bv1 = (gn < Nc) ? *(const uint4*)(Bb + (size_t)(kk + jd1_k) * Nc + gn) : z;
        }

        const uint32_t abase = sptr(&As[buf][0]);
        const uint32_t bbase = sptr(&Bs[buf][0]);
#pragma unroll
        for (int h = 0; h < 2; h++) {
            uint32_t afr0[4], afr1[4];
            int arow = warp_m + (lane & 15);
            uint32_t ad0 = abase + (uint32_t)(arow * (A_PAD * 2) + h * 32 + (lane >> 4) * 16);
            uint32_t ad1 = ad0 + 16 * (A_PAD * 2);
            ldsm4(afr0, ad0);
            ldsm4(afr1, ad1);
#pragma unroll
            for (int nt = 0; nt < 4; nt++) {
                uint32_t bfr[4];
                uint32_t bd = bbase
                    + (uint32_t)((h * 16 + (lane & 15)) * (B_PAD * 2)
                    + (warp_n + nt * 16 + ((lane >> 4) << 3)) * 2);
                ldsm4t(bfr, bd);
                mma16816(acc[0][nt * 2],     afr0, bfr[0], bfr[1]);
                mma16816(acc[0][nt * 2 + 1], afr0, bfr[2], bfr[3]);
                mma16816(acc[1][nt * 2],     afr1, bfr[0], bfr[1]);
                mma16816(acc[1][nt * 2 + 1], afr1, bfr[2], bfr[3]);
            }
        }

        if (pf) {
            int nb = buf ^ 1;
            *(uint4*)(&As[nb][id0_row * A_PAD + id0_c * 8]) = av0;
            *(uint4*)(&As[nb][id1_row * A_PAD + id1_c * 8]) = av1;
            *(uint4*)(&Bs[nb][jd0_k * B_PAD + jd0_c * 8]) = bv0;
            *(uint4*)(&Bs[nb][jd1_k * B_PAD + jd1_c * 8]) = bv1;
        }
        __syncthreads();
        buf ^= 1;
    }

#pragma unroll
    for (int mt = 0; mt < 2; mt++) {
#pragma unroll
        for (int n8 = 0; n8 < 8; n8++) {
            int col = bn + warp_n + n8 * 8 + (lane & 3) * 2;
            if (col >= Nc) continue;
            float bb0 = 0.f, bb1 = 0.f;
            if (bias) { bb0 = bias[col]; bb1 = bias[col + 1]; }
            int row0 = bm + warp_m + mt * 16 + (lane >> 2);
            float v0 = acc[mt][n8][0] + bb0;
            float v1 = acc[mt][n8][1] + bb1;
            float v2 = acc[mt][n8][2] + bb0;
            float v3 = acc[mt][n8][3] + bb1;
            if (act) {
                v0 = fmaxf(v0, 0.f); v1 = fmaxf(v1, 0.f);
                v2 = fmaxf(v2, 0.f); v3 = fmaxf(v3, 0.f);
            }
            if (row0 < M) {
                size_t o = (size_t)row0 * Nc + col;
                if (Cf) {
                    float2 p; p.x = v0; p.y = v1;
                    *(float2*)&Cf[o] = p;
                } else {
                    __nv_bfloat16 h0 = __float2bfloat16(v0);
                    __nv_bfloat16 h1 = __float2bfloat16(v1);
                    __nv_bfloat162 hp; hp.x = h0; hp.y = h1;
                    *(__nv_bfloat162*)&c_hi[o] = hp;
                    __nv_bfloat162 lp;
                    lp.x = __float2bfloat16(v0 - __bfloat162float(h0));
                    lp.y = __float2bfloat16(v1 - __bfloat162float(h1));
                    *(__nv_bfloat162*)&c_lo[o] = lp;
                }
            }
            int row1 = row0 + 8;
            if (row1 < M) {
                size_t o = (size_t)row1 * Nc + col;
                if (Cf) {
                    float2 p; p.x = v2; p.y = v3;
                    *(float2*)&Cf[o] = p;
                } else {
                    __nv_bfloat16 h0 = __float2bfloat16(v2);
                    __nv_bfloat16 h1 = __float2bfloat16(v3);
                    __nv_bfloat162 hp; hp.x = h0; hp.y = h1;
                    *(__nv_bfloat162*)&c_hi[o] = hp;
                    __nv_bfloat162 lp;
                    lp.x = __float2bfloat16(v2 - __bfloat162float(h0));
                    lp.y = __float2bfloat16(v3 - __bfloat162float(h1));
                    *(__nv_bfloat162*)&c_lo[o] = lp;
                }
            }
        }
    }
}

// ---------------- attention scores (no atomics) ----------------
__global__ void score_kernel(const float* __restrict__ xh,
                             const float* __restrict__ asrc,
                             const float* __restrict__ adst,
                             float* __restrict__ ssrc, float* __restrict__ sdst, int H)
{
    int w = (blockIdx.x * blockDim.x + threadIdx.x) >> 5;
    int lane = threadIdx.x & 31;
    if (w >= NN * H) return;
    int n = w / H, h = w - n * H;
    int F = H * 64;
    const float* row = xh + (size_t)n * F + h * 64;
    float x0 = row[lane], x1 = row[lane + 32];
    float vs = x0 * asrc[h * 64 + lane] + x1 * asrc[h * 64 + lane + 32];
    float vd = x0 * adst[h * 64 + lane] + x1 * adst[h * 64 + lane + 32];
#pragma unroll
    for (int o = 16; o; o >>= 1) {
        vs += __shfl_xor_sync(0xffffffffu, vs, o);
        vd += __shfl_xor_sync(0xffffffffu, vd, o);
    }
    if (lane == 0) { ssrc[w] = vs; sdst[w] = vd; }
}

// ---------------- two-pass segment-softmax aggregation ----------------
__global__ void agg_kernel(const float* __restrict__ xh,
                           const float* __restrict__ ssrc,
                           const float* __restrict__ sdst,
                           float* __restrict__ agg, int H)
{
    int w = (blockIdx.x * blockDim.x + threadIdx.x) >> 5;
    int lane = threadIdx.x & 31;
    if (w >= NN * H) return;
    int n = w / H, h = w - n * H;
    int F = H * 64;
    int start = g_off[n], end = g_off[n + 1];
    float sd = sdst[n * H + h];
    float eself = lrelu(ssrc[n * H + h] + sd);

    float m = eself;
    for (int j = start + lane; j < end; j += 32) {
        int s = g_adj[j];
        m = fmaxf(m, lrelu(ssrc[s * H + h] + sd));
    }
#pragma unroll
    for (int o = 16; o; o >>= 1) m = fmaxf(m, __shfl_xor_sync(0xffffffffu, m, o));

    float wself = __expf(eself - m);
    float zpart = (lane == 0) ? wself : 0.f;
    const float* selfrow = xh + (size_t)n * F + h * 64;
    float acc0 = wself * selfrow[lane];
    float acc1 = wself * selfrow[lane + 32];

    for (int j0 = start; j0 < end; j0 += 32) {
        int j = j0 + lane;
        int s = (j < end) ? g_adj[j] : n;
        float wv = 0.f;
        if (j < end) {
            wv = __expf(lrelu(ssrc[s * H + h] + sd) - m);
            zpart += wv;
        }
        int cnt = min(32, end - j0);
        for (int k = 0; k < cnt; k++) {
            float wk = __shfl_sync(0xffffffffu, wv, k);
            int   sk = __shfl_sync(0xffffffffu, s, k);
            const float* r = xh + (size_t)sk * F + h * 64;
            acc0 = fmaf(wk, r[lane], acc0);
            acc1 = fmaf(wk, r[lane + 32], acc1);
        }
    }
#pragma unroll
    for (int o = 16; o; o >>= 1) zpart += __shfl_xor_sync(0xffffffffu, zpart, o);
    float inv = 1.f / zpart;
    agg[(size_t)n * F + h * 64 + lane]      = acc0 * inv;
    agg[(size_t)n * F + h * 64 + lane + 32] = acc1 * inv;
}

// ---------------- epilogues ----------------
__global__ void bias_elu_split4_kernel(const float4* __restrict__ in, const float* __restrict__ b,
                                       __nv_bfloat162* __restrict__ hi, __nv_bfloat162* __restrict__ lo,
                                       int n4, int Fmask4) {
    int i = blockIdx.x * blockDim.x + threadIdx.x;
    if (i < n4) {
        float4 f = in[i];
        int bidx = (i & Fmask4) * 4;
        float v0 = elu1(f.x + b[bidx]);
        float v1 = elu1(f.y + b[bidx + 1]);
        float v2 = elu1(f.z + b[bidx + 2]);
        float v3 = elu1(f.w + b[bidx + 3]);
        __nv_bfloat16 h0 = __float2bfloat16(v0);
        __nv_bfloat16 h1 = __float2bfloat16(v1);
        __nv_bfloat16 h2 = __float2bfloat16(v2);
        __nv_bfloat16 h3 = __float2bfloat16(v3);
        __nv_bfloat162 a0; a0.x = h0; a0.y = h1;
        __nv_bfloat162 a1; a1.x = h2; a1.y = h3;
        hi[i * 2]     = a0;
        hi[i * 2 + 1] = a1;
        __nv_bfloat162 l0, l1;
        l0.x = __float2bfloat16(v0 - __bfloat162float(h0));
        l0.y = __float2bfloat16(v1 - __bfloat162float(h1));
        l1.x = __float2bfloat16(v2 - __bfloat162float(h2));
        l1.y = __float2bfloat16(v3 - __bfloat162float(h3));
        lo[i * 2]     = l0;
        lo[i * 2 + 1] = l1;
    }
}

__global__ void mean2_bias_elu_split_kernel(const float* __restrict__ in, const float* __restrict__ b,
                                            __nv_bfloat16* __restrict__ hi, __nv_bfloat16* __restrict__ lo,
                                            int total) {
    int i = blockIdx.x * blockDim.x + threadIdx.x;
    if (i < total) {
        int n = i >> 6, d = i & 63;
        float v = 0.5f * (in[(size_t)n * 128 + d] + in[(size_t)n * 128 + 64 + d]) + b[d];
        v = elu1(v);
        __nv_bfloat16 h = __float2bfloat16(v);
        hi[i] = h;
        lo[i] = __float2bfloat16(v - __bfloat162float(h));
    }
}

__global__ void final_bias_kernel(const float* __restrict__ in, const float* __restrict__ b,
                                  float* __restrict__ out, int total) {
    int i = blockIdx.x * blockDim.x + threadIdx.x;
    if (i < total) out[i] = in[i] + b[i & 63];
}

// ---------------- host ----------------
extern "C" void kernel_launch(void* const* d_in, const int* in_sizes, int n_in,
                              void* d_out, int out_size) {
    const float* x     = (const float*)d_in[0];
    const int*   ei    = (const int*)  d_in[1];
    const float* w1    = (const float*)d_in[2];
    const float* b1    = (const float*)d_in[3];
    const float* w2    = (const float*)d_in[4];
    const float* b2    = (const float*)d_in[5];
    const float* g1w   = (const float*)d_in[6];
    const float* g1as  = (const float*)d_in[7];
    const float* g1ad  = (const float*)d_in[8];
    const float* g1b   = (const float*)d_in[9];
    const float* g2w   = (const float*)d_in[10];
    const float* g2as  = (const float*)d_in[11];
    const float* g2ad  = (const float*)d_in[12];
    const float* g2b   = (const float*)d_in[13];
    const float* g3w   = (const float*)d_in[14];
    const float* g3as  = (const float*)d_in[15];
    const float* g3ad  = (const float*)d_in[16];
    const float* g3b   = (const float*)d_in[17];

    int E = in_sizes[1] / 2;
    if (E > EMAX) E = EMAX;
    const int* srcp = ei;
    const int* dstp = ei + E;

    float *xh, *agg, *ssrc, *sdst;
    int *deg, *cur;
    __nv_bfloat16 *Phi, *Plo, *Qhi, *Qlo, *whi, *wlo;
    cudaGetSymbolAddress((void**)&xh,   g_xh);
    cudaGetSymbolAddress((void**)&agg,  g_agg);
    cudaGetSymbolAddress((void**)&ssrc, g_ssrc);
    cudaGetSymbolAddress((void**)&sdst, g_sdst);
    cudaGetSymbolAddress((void**)&deg,  g_deg);
    cudaGetSymbolAddress((void**)&cur,  g_cur);
    cudaGetSymbolAddress((void**)&Phi,  g_Phi);
    cudaGetSymbolAddress((void**)&Plo,  g_Plo);
    cudaGetSymbolAddress((void**)&Qhi,  g_Qhi);
    cudaGetSymbolAddress((void**)&Qlo,  g_Qlo);
    cudaGetSymbolAddress((void**)&whi,  g_whi);
    cudaGetSymbolAddress((void**)&wlo,  g_wlo);

    const int OW1 = 0, OW2 = 32768, OG1 = 49152, OG2 = 81920, OG3 = 114688;

    // ---- CSR build ----
    cudaMemsetAsync(deg, 0, NN * sizeof(int));
    cudaMemsetAsync(cur, 0, NN * sizeof(int));
    deg_kernel<<<(E + 255) / 256, 256>>>(dstp, E);
    scan_kernel<<<1, 1024>>>(NN);
    scatter_kernel<<<(E + 255) / 256, 256>>>(srcp, dstp, E);

    // ---- all splits upfront (x + 5 weights) ----
    {
        int n4 = NN * 256 / 4;
        split4_kernel<<<(n4 + 255) / 256, 256>>>((const float4*)x, (__nv_bfloat162*)Phi, (__nv_bfloat162*)Plo, n4);
        split4_kernel<<<(32768/4 + 255) / 256, 256>>>((const float4*)w1,  (__nv_bfloat162*)(whi + OW1), (__nv_bfloat162*)(wlo + OW1), 32768/4);
        split4_kernel<<<(16384/4 + 255) / 256, 256>>>((const float4*)w2,  (__nv_bfloat162*)(whi + OW2), (__nv_bfloat162*)(wlo + OW2), 16384/4);
        split4_kernel<<<(32768/4 + 255) / 256, 256>>>((const float4*)g1w, (__nv_bfloat162*)(whi + OG1), (__nv_bfloat162*)(wlo + OG1), 32768/4);
        split4_kernel<<<(32768/4 + 255) / 256, 256>>>((const float4*)g2w, (__nv_bfloat162*)(whi + OG2), (__nv_bfloat162*)(wlo + OG2), 32768/4);
        split4_kernel<<<(4096/4 + 255) / 256, 256>>>((const float4*)g3w,  (__nv_bfloat162*)(whi + OG3), (__nv_bfloat162*)(wlo + OG3), 4096/4);
    }

    const int GY = (NN + 127) / 128;   // 391

    // ---- semantic MLP ----
    tgemm_kernel<<<dim3(1, GY), 256>>>(Phi, Plo, whi + OW1, wlo + OW1, b1, nullptr, Qhi, Qlo, NN, 256, 128, 1);
    tgemm_kernel<<<dim3(1, GY), 256>>>(Qhi, Qlo, whi + OW2, wlo + OW2, b2, nullptr, Phi, Plo, NN, 128, 128, 1);

    // ---- GAT 1: 128 -> 4 heads x 64, concat, elu ----
    tgemm_kernel<<<dim3(2, GY), 256>>>(Phi, Plo, whi + OG1, wlo + OG1, nullptr, xh, nullptr, nullptr, NN, 128, 256, 0);
    {
        int W = NN * 4;
        score_kernel<<<(W * 32 + 255) / 256, 256>>>(xh, g1as, g1ad, ssrc, sdst, 4);
        agg_kernel  <<<(W * 32 + 255) / 256, 256>>>(xh, ssrc, sdst, agg, 4);
        int n4 = NN * 256 / 4;
        bias_elu_split4_kernel<<<(n4 + 255) / 256, 256>>>((const float4*)agg, g1b,
            (__nv_bfloat162*)Qhi, (__nv_bfloat162*)Qlo, n4, 63);
    }

    // ---- GAT 2: 256 -> 2 heads x 64, mean, elu ----
    tgemm_kernel<<<dim3(1, GY), 256>>>(Qhi, Qlo, whi + OG2, wlo + OG2, nullptr, xh, nullptr, nullptr, NN, 256, 128, 0);
    {
        int W = NN * 2;
        score_kernel<<<(W * 32 + 255) / 256, 256>>>(xh, g2as, g2ad, ssrc, sdst, 2);
        agg_kernel  <<<(W * 32 + 255) / 256, 256>>>(xh, ssrc, sdst, agg, 2);
        int tot = NN * 64;
        mean2_bias_elu_split_kernel<<<(tot + 1023) / 1024, 1024>>>(agg, g2b, Phi, Plo, tot);
    }

    // ---- GAT 3: 64 -> 1 head x 64 ----
    tgemm_kernel<<<dim3(1, GY), 256>>>(Phi, Plo, whi + OG3, wlo + OG3, nullptr, xh, nullptr, nullptr, NN, 64, 64, 0);
    {
        int W = NN;
        score_kernel<<<(W * 32 + 255) / 256, 256>>>(xh, g3as, g3ad, ssrc, sdst, 1);
        agg_kernel  <<<(W * 32 + 255) / 256, 256>>>(xh, ssrc, sdst, agg, 1);
        int tot = NN * 64;
        final_bias_kernel<<<(tot + 1023) / 1024, 1024>>>(agg, g3b, (float*)d_out, tot);
    }
}

// round 13
// speedup vs baseline: 1.3604x; 1.0301x over previous
#include <cuda_runtime.h>
#include <cuda_bf16.h>
#include <cstdint>
#include <cstddef>

#define NN 50000
#define EMAX 800000

// ---------------- scratch (device globals; no allocation allowed) ----------------
__device__ float g_xh[(size_t)NN * 256];
__device__ float g_agg[(size_t)NN * 256];
__device__ float g_ssrc[NN * 4];
__device__ float g_sdst[NN * 4];
__device__ int   g_off[NN + 1];
__device__ int   g_deg[NN];
__device__ int   g_cur[NN];
__device__ int   g_adj[EMAX];

// split bf16 buffers
__device__ __align__(16) __nv_bfloat16 g_Phi[(size_t)NN * 256];
__device__ __align__(16) __nv_bfloat16 g_Plo[(size_t)NN * 256];
__device__ __align__(16) __nv_bfloat16 g_Qhi[(size_t)NN * 256];
__device__ __align__(16) __nv_bfloat16 g_Qlo[(size_t)NN * 256];
__device__ __align__(16) __nv_bfloat16 g_whi[131072];
__device__ __align__(16) __nv_bfloat16 g_wlo[131072];

__device__ __forceinline__ float lrelu(float x) { return fmaxf(x, 0.2f * x); }
__device__ __forceinline__ float elu1(float x)  { return x > 0.f ? x : expm1f(x); }

// ---------------- CSR build ----------------
__global__ void deg_kernel(const int* __restrict__ dst, int E) {
    int i = blockIdx.x * blockDim.x + threadIdx.x;
    if (i < E) atomicAdd(&g_deg[dst[i]], 1);
}

__global__ void scan_kernel(int n) {
    __shared__ int s[1024];
    int tid = threadIdx.x;
    const int chunk = (n + 1023) / 1024;
    int begin = tid * chunk;
    int endi  = min(begin + chunk, n);
    int sum = 0;
    for (int i = begin; i < endi; i++) sum += g_deg[i];
    s[tid] = sum;
    __syncthreads();
    for (int off = 1; off < 1024; off <<= 1) {
        int v = (tid >= off) ? s[tid - off] : 0;
        __syncthreads();
        s[tid] += v;
        __syncthreads();
    }
    int run = (tid == 0) ? 0 : s[tid - 1];
    for (int i = begin; i < endi; i++) { g_off[i] = run; run += g_deg[i]; }
    if (tid == 1023) g_off[n] = s[1023];
}

__global__ void scatter_kernel(const int* __restrict__ src, const int* __restrict__ dst, int E) {
    int i = blockIdx.x * blockDim.x + threadIdx.x;
    if (i < E) {
        int d = dst[i];
        int pos = g_off[d] + atomicAdd(&g_cur[d], 1);
        g_adj[pos] = src[i];
    }
}

// ---------------- vectorized fp32 -> bf16 hi/lo split (4 elems/thread) ----------------
__global__ void split4_kernel(const float4* __restrict__ a,
                              __nv_bfloat162* __restrict__ hi,
                              __nv_bfloat162* __restrict__ lo, int n4) {
    int i = blockIdx.x * blockDim.x + threadIdx.x;
    if (i < n4) {
        float4 f = a[i];
        __nv_bfloat16 h0 = __float2bfloat16(f.x);
        __nv_bfloat16 h1 = __float2bfloat16(f.y);
        __nv_bfloat16 h2 = __float2bfloat16(f.z);
        __nv_bfloat16 h3 = __float2bfloat16(f.w);
        __nv_bfloat162 a0; a0.x = h0; a0.y = h1;
        __nv_bfloat162 a1; a1.x = h2; a1.y = h3;
        hi[i * 2]     = a0;
        hi[i * 2 + 1] = a1;
        __nv_bfloat162 l0, l1;
        l0.x = __float2bfloat16(f.x - __bfloat162float(h0));
        l0.y = __float2bfloat16(f.y - __bfloat162float(h1));
        l1.x = __float2bfloat16(f.z - __bfloat162float(h2));
        l1.y = __float2bfloat16(f.w - __bfloat162float(h3));
        lo[i * 2]     = l0;
        lo[i * 2 + 1] = l1;
    }
}

// ---------------- tensor-core GEMM with split-bf16 operands + fused scores ----------------
__device__ __forceinline__ uint32_t sptr(const void* p) {
    return (uint32_t)__cvta_generic_to_shared(p);
}
__device__ __forceinline__ void ldsm4(uint32_t* r, uint32_t a) {
    asm volatile("ldmatrix.sync.aligned.m8n8.x4.shared.b16 {%0,%1,%2,%3},[%4];\n"
                 : "=r"(r[0]), "=r"(r[1]), "=r"(r[2]), "=r"(r[3]) : "r"(a));
}
__device__ __forceinline__ void ldsm4t(uint32_t* r, uint32_t a) {
    asm volatile("ldmatrix.sync.aligned.m8n8.x4.trans.shared.b16 {%0,%1,%2,%3},[%4];\n"
                 : "=r"(r[0]), "=r"(r[1]), "=r"(r[2]), "=r"(r[3]) : "r"(a));
}
__device__ __forceinline__ void mma16816(float* d, const uint32_t* a, uint32_t b0, uint32_t b1) {
    asm volatile("mma.sync.aligned.m16n8k16.row.col.f32.bf16.bf16.f32 "
                 "{%0,%1,%2,%3},{%4,%5,%6,%7},{%8,%9},{%0,%1,%2,%3};\n"
                 : "+f"(d[0]), "+f"(d[1]), "+f"(d[2]), "+f"(d[3])
                 : "r"(a[0]), "r"(a[1]), "r"(a[2]), "r"(a[3]), "r"(b0), "r"(b1));
}

#define A_PAD 40
#define B_PAD 136

// When asrc != nullptr (GAT mode, Cf output): each head's 64 columns are fully
// contained in one warp's 64-col slice; score dot-products are computed from the
// in-register accumulators (4-lane shfl reduction), written directly to ssrc/sdst.
__global__ __launch_bounds__(256, 2) void tgemm_kernel(
    const __nv_bfloat16* __restrict__ a_hi, const __nv_bfloat16* __restrict__ a_lo,
    const __nv_bfloat16* __restrict__ b_hi, const __nv_bfloat16* __restrict__ b_lo,
    const float* __restrict__ bias,
    float* __restrict__ Cf,
    __nv_bfloat16* __restrict__ c_hi, __nv_bfloat16* __restrict__ c_lo,
    const float* __restrict__ asrc, const float* __restrict__ adst,
    float* __restrict__ ssrc, float* __restrict__ sdst, int H,
    int M, int K, int Nc, int act)
{
    __shared__ __align__(16) __nv_bfloat16 As[2][128 * A_PAD];
    __shared__ __align__(16) __nv_bfloat16 Bs[2][32 * B_PAD];

    const int tid  = threadIdx.x;
    const int wid  = tid >> 5;
    const int lane = tid & 31;
    const int warp_m = (wid & 3) * 32;
    const int warp_n = (wid >> 2) * 64;
    const int bm = blockIdx.y * 128;
    const int bn = blockIdx.x * 128;

    const int id0_row = tid >> 2,          id0_c = tid & 3;
    const int id1_row = (tid + 256) >> 2,  id1_c = tid & 3;
    const int jd0_k   = tid >> 4,          jd0_c = tid & 15;
    const int jd1_k   = (tid + 256) >> 4,  jd1_c = tid & 15;

    const int nst = (3 * K) >> 5;

    {
        const __nv_bfloat16* Ab = a_hi;
        const __nv_bfloat16* Bb = b_hi;
        uint4 z = make_uint4(0, 0, 0, 0);
        uint4 v;
        int gm = bm + id0_row;
        v = (gm < M) ? *(const uint4*)(Ab + (size_t)gm * K + id0_c * 8) : z;
        *(uint4*)(&As[0][id0_row * A_PAD + id0_c * 8]) = v;
        gm = bm + id1_row;
        v = (gm < M) ? *(const uint4*)(Ab + (size_t)gm * K + id1_c * 8) : z;
        *(uint4*)(&As[0][id1_row * A_PAD + id1_c * 8]) = v;
        int gn = bn + jd0_c * 8;
        v = (gn < Nc) ? *(const uint4*)(Bb + (size_t)jd0_k * Nc + gn) : z;
        *(uint4*)(&Bs[0][jd0_k * B_PAD + jd0_c * 8]) = v;
        gn = bn + jd1_c * 8;
        v = (gn < Nc) ? *(const uint4*)(Bb + (size_t)jd1_k * Nc + gn) : z;
        *(uint4*)(&Bs[0][jd1_k * B_PAD + jd1_c * 8]) = v;
    }
    __syncthreads();

    float acc[2][8][4];
#pragma unroll
    for (int mt = 0; mt < 2; mt++)
#pragma unroll
        for (int n8 = 0; n8 < 8; n8++)
#pragma unroll
            for (int r = 0; r < 4; r++) acc[mt][n8][r] = 0.f;

    int buf = 0;
    for (int s = 0; s < nst; s++) {
        const bool pf = (s + 1) < nst;
        uint4 av0, av1, bv0, bv1;
        if (pf) {
            int k0 = (s + 1) * 32;
            int rg = k0 / K;
            int kk = k0 - rg * K;
            const __nv_bfloat16* Ab = (rg == 1) ? a_lo : a_hi;
            const __nv_bfloat16* Bb = (rg == 2) ? b_lo : b_hi;
            uint4 z = make_uint4(0, 0, 0, 0);
            int gm = bm + id0_row;
            av0 = (gm < M) ? *(const uint4*)(Ab + (size_t)gm * K + kk + id0_c * 8) : z;
            gm = bm + id1_row;
            av1 = (gm < M) ? *(const uint4*)(Ab + (size_t)gm * K + kk + id1_c * 8) : z;
            int gn = bn + jd0_c * 8;
            bv0 = (gn < Nc) ? *(const uint4*)(Bb + (size_t)(kk + jd0_k) * Nc + gn) : z;
            gn = bn + jd1_c * 8;
            bv1 = (gn < Nc) ? *(const uint4*)(Bb + (size_t)(kk + jd1_k) * Nc + gn) : z;
        }

        const uint32_t abase = sptr(&As[buf][0]);
        const uint32_t bbase = sptr(&Bs[buf][0]);
#pragma unroll
        for (int h = 0; h < 2; h++) {
            uint32_t afr0[4], afr1[4];
            int arow = warp_m + (lane & 15);
            uint32_t ad0 = abase + (uint32_t)(arow * (A_PAD * 2) + h * 32 + (lane >> 4) * 16);
            uint32_t ad1 = ad0 + 16 * (A_PAD * 2);
            ldsm4(afr0, ad0);
            ldsm4(afr1, ad1);
#pragma unroll
            for (int nt = 0; nt < 4; nt++) {
                uint32_t bfr[4];
                uint32_t bd = bbase
                    + (uint32_t)((h * 16 + (lane & 15)) * (B_PAD * 2)
                    + (warp_n + nt * 16 + ((lane >> 4) << 3)) * 2);
                ldsm4t(bfr, bd);
                mma16816(acc[0][nt * 2],     afr0, bfr[0], bfr[1]);
                mma16816(acc[0][nt * 2 + 1], afr0, bfr[2], bfr[3]);
                mma16816(acc[1][nt * 2],     afr1, bfr[0], bfr[1]);
                mma16816(acc[1][nt * 2 + 1], afr1, bfr[2], bfr[3]);
            }
        }

        if (pf) {
            int nb = buf ^ 1;
            *(uint4*)(&As[nb][id0_row * A_PAD + id0_c * 8]) = av0;
            *(uint4*)(&As[nb][id1_row * A_PAD + id1_c * 8]) = av1;
            *(uint4*)(&Bs[nb][jd0_k * B_PAD + jd0_c * 8]) = bv0;
            *(uint4*)(&Bs[nb][jd1_k * B_PAD + jd1_c * 8]) = bv1;
        }
        __syncthreads();
        buf ^= 1;
    }

    // ---- epilogue (+ fused attention scores) ----
    float ss[2][2] = {{0.f, 0.f}, {0.f, 0.f}};
    float dd[2][2] = {{0.f, 0.f}, {0.f, 0.f}};
#pragma unroll
    for (int mt = 0; mt < 2; mt++) {
#pragma unroll
        for (int n8 = 0; n8 < 8; n8++) {
            int col = bn + warp_n + n8 * 8 + (lane & 3) * 2;
            if (col >= Nc) continue;
            float bb0 = 0.f, bb1 = 0.f;
            if (bias) { bb0 = bias[col]; bb1 = bias[col + 1]; }
            int row0 = bm + warp_m + mt * 16 + (lane >> 2);
            float v0 = acc[mt][n8][0] + bb0;
            float v1 = acc[mt][n8][1] + bb1;
            float v2 = acc[mt][n8][2] + bb0;
            float v3 = acc[mt][n8][3] + bb1;
            if (act) {
                v0 = fmaxf(v0, 0.f); v1 = fmaxf(v1, 0.f);
                v2 = fmaxf(v2, 0.f); v3 = fmaxf(v3, 0.f);
            }
            if (asrc) {
                float as0 = asrc[col], as1 = asrc[col + 1];
                float ad0 = adst[col], ad1 = adst[col + 1];
                ss[mt][0] += v0 * as0 + v1 * as1;
                ss[mt][1] += v2 * as0 + v3 * as1;
                dd[mt][0] += v0 * ad0 + v1 * ad1;
                dd[mt][1] += v2 * ad0 + v3 * ad1;
            }
            if (row0 < M) {
                size_t o = (size_t)row0 * Nc + col;
                if (Cf) {
                    float2 p; p.x = v0; p.y = v1;
                    *(float2*)&Cf[o] = p;
                } else {
                    __nv_bfloat16 h0 = __float2bfloat16(v0);
                    __nv_bfloat16 h1 = __float2bfloat16(v1);
                    __nv_bfloat162 hp; hp.x = h0; hp.y = h1;
                    *(__nv_bfloat162*)&c_hi[o] = hp;
                    __nv_bfloat162 lp;
                    lp.x = __float2bfloat16(v0 - __bfloat162float(h0));
                    lp.y = __float2bfloat16(v1 - __bfloat162float(h1));
                    *(__nv_bfloat162*)&c_lo[o] = lp;
                }
            }
            int row1 = row0 + 8;
            if (row1 < M) {
                size_t o = (size_t)row1 * Nc + col;
                if (Cf) {
                    float2 p; p.x = v2; p.y = v3;
                    *(float2*)&Cf[o] = p;
                } else {
                    __nv_bfloat16 h0 = __float2bfloat16(v2);
                    __nv_bfloat16 h1 = __float2bfloat16(v3);
                    __nv_bfloat162 hp; hp.x = h0; hp.y = h1;
                    *(__nv_bfloat162*)&c_hi[o] = hp;
                    __nv_bfloat162 lp;
                    lp.x = __float2bfloat16(v2 - __bfloat162float(h0));
                    lp.y = __float2bfloat16(v3 - __bfloat162float(h1));
                    *(__nv_bfloat162*)&c_lo[o] = lp;
                }
            }
        }
    }

    if (asrc && (bn + warp_n) < Nc) {
        int h = (bn + warp_n) >> 6;   // head fully owned by this warp slice
#pragma unroll
        for (int mt = 0; mt < 2; mt++) {
#pragma unroll
            for (int r = 0; r < 2; r++) {
                float vs = ss[mt][r];
                float vd = dd[mt][r];
                vs += __shfl_xor_sync(0xffffffffu, vs, 1);
                vs += __shfl_xor_sync(0xffffffffu, vs, 2);
                vd += __shfl_xor_sync(0xffffffffu, vd, 1);
                vd += __shfl_xor_sync(0xffffffffu, vd, 2);
                int row = bm + warp_m + mt * 16 + (lane >> 2) + r * 8;
                if ((lane & 3) == 0 && row < M) {
                    ssrc[row * H + h] = vs;
                    sdst[row * H + h] = vd;
                }
            }
        }
    }
}

// ---------------- two-pass segment-softmax aggregation ----------------
__global__ void agg_kernel(const float* __restrict__ xh,
                           const float* __restrict__ ssrc,
                           const float* __restrict__ sdst,
                           float* __restrict__ agg, int H)
{
    int w = (blockIdx.x * blockDim.x + threadIdx.x) >> 5;
    int lane = threadIdx.x & 31;
    if (w >= NN * H) return;
    int n = w / H, h = w - n * H;
    int F = H * 64;
    int start = g_off[n], end = g_off[n + 1];
    float sd = sdst[n * H + h];
    float eself = lrelu(ssrc[n * H + h] + sd);

    float m = eself;
    for (int j = start + lane; j < end; j += 32) {
        int s = g_adj[j];
        m = fmaxf(m, lrelu(ssrc[s * H + h] + sd));
    }
#pragma unroll
    for (int o = 16; o; o >>= 1) m = fmaxf(m, __shfl_xor_sync(0xffffffffu, m, o));

    float wself = __expf(eself - m);
    float zpart = (lane == 0) ? wself : 0.f;
    const float* selfrow = xh + (size_t)n * F + h * 64;
    float acc0 = wself * selfrow[lane];
    float acc1 = wself * selfrow[lane + 32];

    for (int j0 = start; j0 < end; j0 += 32) {
        int j = j0 + lane;
        int s = (j < end) ? g_adj[j] : n;
        float wv = 0.f;
        if (j < end) {
            wv = __expf(lrelu(ssrc[s * H + h] + sd) - m);
            zpart += wv;
        }
        int cnt = min(32, end - j0);
        for (int k = 0; k < cnt; k++) {
            float wk = __shfl_sync(0xffffffffu, wv, k);
            int   sk = __shfl_sync(0xffffffffu, s, k);
            const float* r = xh + (size_t)sk * F + h * 64;
            acc0 = fmaf(wk, r[lane], acc0);
            acc1 = fmaf(wk, r[lane + 32], acc1);
        }
    }
#pragma unroll
    for (int o = 16; o; o >>= 1) zpart += __shfl_xor_sync(0xffffffffu, zpart, o);
    float inv = 1.f / zpart;
    agg[(size_t)n * F + h * 64 + lane]      = acc0 * inv;
    agg[(size_t)n * F + h * 64 + lane + 32] = acc1 * inv;
}

// ---------------- epilogues ----------------
__global__ void bias_elu_split4_kernel(const float4* __restrict__ in, const float* __restrict__ b,
                                       __nv_bfloat162* __restrict__ hi, __nv_bfloat162* __restrict__ lo,
                                       int n4, int Fmask4) {
    int i = blockIdx.x * blockDim.x + threadIdx.x;
    if (i < n4) {
        float4 f = in[i];
        int bidx = (i & Fmask4) * 4;
        float v0 = elu1(f.x + b[bidx]);
        float v1 = elu1(f.y + b[bidx + 1]);
        float v2 = elu1(f.z + b[bidx + 2]);
        float v3 = elu1(f.w + b[bidx + 3]);
        __nv_bfloat16 h0 = __float2bfloat16(v0);
        __nv_bfloat16 h1 = __float2bfloat16(v1);
        __nv_bfloat16 h2 = __float2bfloat16(v2);
        __nv_bfloat16 h3 = __float2bfloat16(v3);
        __nv_bfloat162 a0; a0.x = h0; a0.y = h1;
        __nv_bfloat162 a1; a1.x = h2; a1.y = h3;
        hi[i * 2]     = a0;
        hi[i * 2 + 1] = a1;
        __nv_bfloat162 l0, l1;
        l0.x = __float2bfloat16(v0 - __bfloat162float(h0));
        l0.y = __float2bfloat16(v1 - __bfloat162float(h1));
        l1.x = __float2bfloat16(v2 - __bfloat162float(h2));
        l1.y = __float2bfloat16(v3 - __bfloat162float(h3));
        lo[i * 2]     = l0;
        lo[i * 2 + 1] = l1;
    }
}

__global__ void mean2_bias_elu_split_kernel(const float* __restrict__ in, const float* __restrict__ b,
                                            __nv_bfloat16* __restrict__ hi, __nv_bfloat16* __restrict__ lo,
                                            int total) {
    int i = blockIdx.x * blockDim.x + threadIdx.x;
    if (i < total) {
        int n = i >> 6, d = i & 63;
        float v = 0.5f * (in[(size_t)n * 128 + d] + in[(size_t)n * 128 + 64 + d]) + b[d];
        v = elu1(v);
        __nv_bfloat16 h = __float2bfloat16(v);
        hi[i] = h;
        lo[i] = __float2bfloat16(v - __bfloat162float(h));
    }
}

__global__ void final_bias_kernel(const float* __restrict__ in, const float* __restrict__ b,
                                  float* __restrict__ out, int total) {
    int i = blockIdx.x * blockDim.x + threadIdx.x;
    if (i < total) out[i] = in[i] + b[i & 63];
}

// ---------------- host ----------------
extern "C" void kernel_launch(void* const* d_in, const int* in_sizes, int n_in,
                              void* d_out, int out_size) {
    const float* x     = (const float*)d_in[0];
    const int*   ei    = (const int*)  d_in[1];
    const float* w1    = (const float*)d_in[2];
    const float* b1    = (const float*)d_in[3];
    const float* w2    = (const float*)d_in[4];
    const float* b2    = (const float*)d_in[5];
    const float* g1w   = (const float*)d_in[6];
    const float* g1as  = (const float*)d_in[7];
    const float* g1ad  = (const float*)d_in[8];
    const float* g1b   = (const float*)d_in[9];
    const float* g2w   = (const float*)d_in[10];
    const float* g2as  = (const float*)d_in[11];
    const float* g2ad  = (const float*)d_in[12];
    const float* g2b   = (const float*)d_in[13];
    const float* g3w   = (const float*)d_in[14];
    const float* g3as  = (const float*)d_in[15];
    const float* g3ad  = (const float*)d_in[16];
    const float* g3b   = (const float*)d_in[17];

    int E = in_sizes[1] / 2;
    if (E > EMAX) E = EMAX;
    const int* srcp = ei;
    const int* dstp = ei + E;

    float *xh, *agg, *ssrc, *sdst;
    int *deg, *cur;
    __nv_bfloat16 *Phi, *Plo, *Qhi, *Qlo, *whi, *wlo;
    cudaGetSymbolAddress((void**)&xh,   g_xh);
    cudaGetSymbolAddress((void**)&agg,  g_agg);
    cudaGetSymbolAddress((void**)&ssrc, g_ssrc);
    cudaGetSymbolAddress((void**)&sdst, g_sdst);
    cudaGetSymbolAddress((void**)&deg,  g_deg);
    cudaGetSymbolAddress((void**)&cur,  g_cur);
    cudaGetSymbolAddress((void**)&Phi,  g_Phi);
    cudaGetSymbolAddress((void**)&Plo,  g_Plo);
    cudaGetSymbolAddress((void**)&Qhi,  g_Qhi);
    cudaGetSymbolAddress((void**)&Qlo,  g_Qlo);
    cudaGetSymbolAddress((void**)&whi,  g_whi);
    cudaGetSymbolAddress((void**)&wlo,  g_wlo);

    const int OW1 = 0, OW2 = 32768, OG1 = 49152, OG2 = 81920, OG3 = 114688;
    const int GY = (NN + 127) / 128;   // 391

    // ---- launches 1-5: memsets + first splits (so launch #6 = big tgemm for ncu) ----
    cudaMemsetAsync(deg, 0, NN * sizeof(int));
    cudaMemsetAsync(cur, 0, NN * sizeof(int));
    {
        int n4 = NN * 256 / 4;
        split4_kernel<<<(n4 + 255) / 256, 256>>>((const float4*)x, (__nv_bfloat162*)Phi, (__nv_bfloat162*)Plo, n4);
        split4_kernel<<<(32768/4 + 255) / 256, 256>>>((const float4*)w1,  (__nv_bfloat162*)(whi + OW1), (__nv_bfloat162*)(wlo + OW1), 32768/4);
        split4_kernel<<<(16384/4 + 255) / 256, 256>>>((const float4*)w2,  (__nv_bfloat162*)(whi + OW2), (__nv_bfloat162*)(wlo + OW2), 16384/4);
    }

    // ---- launch #6: MLP GEMM 1 (profiled) ----
    tgemm_kernel<<<dim3(1, GY), 256>>>(Phi, Plo, whi + OW1, wlo + OW1, b1, nullptr, Qhi, Qlo,
                                       nullptr, nullptr, nullptr, nullptr, 0, NN, 256, 128, 1);

    // ---- remaining splits + CSR build ----
    split4_kernel<<<(32768/4 + 255) / 256, 256>>>((const float4*)g1w, (__nv_bfloat162*)(whi + OG1), (__nv_bfloat162*)(wlo + OG1), 32768/4);
    split4_kernel<<<(32768/4 + 255) / 256, 256>>>((const float4*)g2w, (__nv_bfloat162*)(whi + OG2), (__nv_bfloat162*)(wlo + OG2), 32768/4);
    split4_kernel<<<(4096/4 + 255) / 256, 256>>>((const float4*)g3w,  (__nv_bfloat162*)(whi + OG3), (__nv_bfloat162*)(wlo + OG3), 4096/4);
    deg_kernel<<<(E + 255) / 256, 256>>>(dstp, E);
    scan_kernel<<<1, 1024>>>(NN);
    scatter_kernel<<<(E + 255) / 256, 256>>>(srcp, dstp, E);

    // ---- MLP GEMM 2 ----
    tgemm_kernel<<<dim3(1, GY), 256>>>(Qhi, Qlo, whi + OW2, wlo + OW2, b2, nullptr, Phi, Plo,
                                       nullptr, nullptr, nullptr, nullptr, 0, NN, 128, 128, 1);

    // ---- GAT 1: 128 -> 4 heads x 64, concat, elu (scores fused in GEMM) ----
    tgemm_kernel<<<dim3(2, GY), 256>>>(Phi, Plo, whi + OG1, wlo + OG1, nullptr, xh, nullptr, nullptr,
                                       g1as, g1ad, ssrc, sdst, 4, NN, 128, 256, 0);
    {
        int W = NN * 4;
        agg_kernel<<<(W * 32 + 255) / 256, 256>>>(xh, ssrc, sdst, agg, 4);
        int n4 = NN * 256 / 4;
        bias_elu_split4_kernel<<<(n4 + 255) / 256, 256>>>((const float4*)agg, g1b,
            (__nv_bfloat162*)Qhi, (__nv_bfloat162*)Qlo, n4, 63);
    }

    // ---- GAT 2: 256 -> 2 heads x 64, mean, elu ----
    tgemm_kernel<<<dim3(1, GY), 256>>>(Qhi, Qlo, whi + OG2, wlo + OG2, nullptr, xh, nullptr, nullptr,
                                       g2as, g2ad, ssrc, sdst, 2, NN, 256, 128, 0);
    {
        int W = NN * 2;
        agg_kernel<<<(W * 32 + 255) / 256, 256>>>(xh, ssrc, sdst, agg, 2);
        int tot = NN * 64;
        mean2_bias_elu_split_kernel<<<(tot + 1023) / 1024, 1024>>>(agg, g2b, Phi, Plo, tot);
    }

    // ---- GAT 3: 64 -> 1 head x 64 ----
    tgemm_kernel<<<dim3(1, GY), 256>>>(Phi, Plo, whi + OG3, wlo + OG3, nullptr, xh, nullptr, nullptr,
                                       g3as, g3ad, ssrc, sdst, 1, NN, 64, 64, 0);
    {
        int W = NN;
        agg_kernel<<<(W * 32 + 255) / 256, 256>>>(xh, ssrc, sdst, agg, 1);
        int tot = NN * 64;
        final_bias_kernel<<<(tot + 1023) / 1024, 1024>>>(agg, g3b, (float*)d_out, tot);
    }
}

// round 16
// speedup vs baseline: 1.5115x; 1.1111x over previous
#include <cuda_runtime.h>
#include <cuda_bf16.h>
#include <cstdint>
#include <cstddef>

#define NN 50000
#define EMAX 800000

// ---------------- scratch (device globals; no allocation allowed) ----------------
__device__ float g_xh[(size_t)NN * 256];
__device__ float g_ssrc[NN * 4];
__device__ float g_sdst[NN * 4];
__device__ int   g_off[NN + 1];
__device__ int   g_deg[NN];
__device__ int   g_cur[NN];
__device__ int   g_adj[EMAX];

// split bf16 buffers
__device__ __align__(16) __nv_bfloat16 g_Phi[(size_t)NN * 256];
__device__ __align__(16) __nv_bfloat16 g_Plo[(size_t)NN * 256];
__device__ __align__(16) __nv_bfloat16 g_Qhi[(size_t)NN * 256];
__device__ __align__(16) __nv_bfloat16 g_Qlo[(size_t)NN * 256];
__device__ __align__(16) __nv_bfloat16 g_whi[131072];
__device__ __align__(16) __nv_bfloat16 g_wlo[131072];

__device__ __forceinline__ float lrelu(float x) { return fmaxf(x, 0.2f * x); }
__device__ __forceinline__ float elu1(float x)  { return x > 0.f ? x : expm1f(x); }

// ---------------- CSR build ----------------
__global__ void deg_kernel(const int* __restrict__ dst, int E) {
    int i = blockIdx.x * blockDim.x + threadIdx.x;
    if (i < E) atomicAdd(&g_deg[dst[i]], 1);
}

__global__ void scan_kernel(int n) {
    __shared__ int s[1024];
    int tid = threadIdx.x;
    const int chunk = (n + 1023) / 1024;
    int begin = tid * chunk;
    int endi  = min(begin + chunk, n);
    int sum = 0;
    for (int i = begin; i < endi; i++) sum += g_deg[i];
    s[tid] = sum;
    __syncthreads();
    for (int off = 1; off < 1024; off <<= 1) {
        int v = (tid >= off) ? s[tid - off] : 0;
        __syncthreads();
        s[tid] += v;
        __syncthreads();
    }
    int run = (tid == 0) ? 0 : s[tid - 1];
    for (int i = begin; i < endi; i++) { g_off[i] = run; run += g_deg[i]; }
    if (tid == 1023) g_off[n] = s[1023];
}

__global__ void scatter_kernel(const int* __restrict__ src, const int* __restrict__ dst, int E) {
    int i = blockIdx.x * blockDim.x + threadIdx.x;
    if (i < E) {
        int d = dst[i];
        int pos = g_off[d] + atomicAdd(&g_cur[d], 1);
        g_adj[pos] = src[i];
    }
}

// ---------------- vectorized fp32 -> bf16 hi/lo split ----------------
__global__ void split4_kernel(const float4* __restrict__ a,
                              __nv_bfloat162* __restrict__ hi,
                              __nv_bfloat162* __restrict__ lo, int n4) {
    int i = blockIdx.x * blockDim.x + threadIdx.x;
    if (i < n4) {
        float4 f = a[i];
        __nv_bfloat16 h0 = __float2bfloat16(f.x);
        __nv_bfloat16 h1 = __float2bfloat16(f.y);
        __nv_bfloat16 h2 = __float2bfloat16(f.z);
        __nv_bfloat16 h3 = __float2bfloat16(f.w);
        __nv_bfloat162 a0; a0.x = h0; a0.y = h1;
        __nv_bfloat162 a1; a1.x = h2; a1.y = h3;
        hi[i * 2]     = a0;
        hi[i * 2 + 1] = a1;
        __nv_bfloat162 l0, l1;
        l0.x = __float2bfloat16(f.x - __bfloat162float(h0));
        l0.y = __float2bfloat16(f.y - __bfloat162float(h1));
        l1.x = __float2bfloat16(f.z - __bfloat162float(h2));
        l1.y = __float2bfloat16(f.w - __bfloat162float(h3));
        lo[i * 2]     = l0;
        lo[i * 2 + 1] = l1;
    }
}

// ---------------- tensor-core GEMM with split-bf16 operands + fused scores ----------------
__device__ __forceinline__ uint32_t sptr(const void* p) {
    return (uint32_t)__cvta_generic_to_shared(p);
}
__device__ __forceinline__ void ldsm4(uint32_t* r, uint32_t a) {
    asm volatile("ldmatrix.sync.aligned.m8n8.x4.shared.b16 {%0,%1,%2,%3},[%4];\n"
                 : "=r"(r[0]), "=r"(r[1]), "=r"(r[2]), "=r"(r[3]) : "r"(a));
}
__device__ __forceinline__ void ldsm4t(uint32_t* r, uint32_t a) {
    asm volatile("ldmatrix.sync.aligned.m8n8.x4.trans.shared.b16 {%0,%1,%2,%3},[%4];\n"
                 : "=r"(r[0]), "=r"(r[1]), "=r"(r[2]), "=r"(r[3]) : "r"(a));
}
__device__ __forceinline__ void mma16816(float* d, const uint32_t* a, uint32_t b0, uint32_t b1) {
    asm volatile("mma.sync.aligned.m16n8k16.row.col.f32.bf16.bf16.f32 "
                 "{%0,%1,%2,%3},{%4,%5,%6,%7},{%8,%9},{%0,%1,%2,%3};\n"
                 : "+f"(d[0]), "+f"(d[1]), "+f"(d[2]), "+f"(d[3])
                 : "r"(a[0]), "r"(a[1]), "r"(a[2]), "r"(a[3]), "r"(b0), "r"(b1));
}

#define A_PAD 40
#define B_PAD 136

__global__ __launch_bounds__(256, 2) void tgemm_kernel(
    const __nv_bfloat16* __restrict__ a_hi, const __nv_bfloat16* __restrict__ a_lo,
    const __nv_bfloat16* __restrict__ b_hi, const __nv_bfloat16* __restrict__ b_lo,
    const float* __restrict__ bias,
    float* __restrict__ Cf,
    __nv_bfloat16* __restrict__ c_hi, __nv_bfloat16* __restrict__ c_lo,
    const float* __restrict__ asrc, const float* __restrict__ adst,
    float* __restrict__ ssrc, float* __restrict__ sdst, int H,
    int M, int K, int Nc, int act)
{
    __shared__ __align__(16) __nv_bfloat16 As[2][128 * A_PAD];
    __shared__ __align__(16) __nv_bfloat16 Bs[2][32 * B_PAD];

    const int tid  = threadIdx.x;
    const int wid  = tid >> 5;
    const int lane = tid & 31;
    const int warp_m = (wid & 3) * 32;
    const int warp_n = (wid >> 2) * 64;
    const int bm = blockIdx.y * 128;
    const int bn = blockIdx.x * 128;

    const int id0_row = tid >> 2,          id0_c = tid & 3;
    const int id1_row = (tid + 256) >> 2,  id1_c = tid & 3;
    const int jd0_k   = tid >> 4,          jd0_c = tid & 15;
    const int jd1_k   = (tid + 256) >> 4,  jd1_c = tid & 15;

    const int nst = (3 * K) >> 5;

    {
        const __nv_bfloat16* Ab = a_hi;
        const __nv_bfloat16* Bb = b_hi;
        uint4 z = make_uint4(0, 0, 0, 0);
        uint4 v;
        int gm = bm + id0_row;
        v = (gm < M) ? *(const uint4*)(Ab + (size_t)gm * K + id0_c * 8) : z;
        *(uint4*)(&As[0][id0_row * A_PAD + id0_c * 8]) = v;
        gm = bm + id1_row;
        v = (gm < M) ? *(const uint4*)(Ab + (size_t)gm * K + id1_c * 8) : z;
        *(uint4*)(&As[0][id1_row * A_PAD + id1_c * 8]) = v;
        int gn = bn + jd0_c * 8;
        v = (gn < Nc) ? *(const uint4*)(Bb + (size_t)jd0_k * Nc + gn) : z;
        *(uint4*)(&Bs[0][jd0_k * B_PAD + jd0_c * 8]) = v;
        gn = bn + jd1_c * 8;
        v = (gn < Nc) ? *(const uint4*)(Bb + (size_t)jd1_k * Nc + gn) : z;
        *(uint4*)(&Bs[0][jd1_k * B_PAD + jd1_c * 8]) = v;
    }
    __syncthreads();

    float acc[2][8][4];
#pragma unroll
    for (int mt = 0; mt < 2; mt++)
#pragma unroll
        for (int n8 = 0; n8 < 8; n8++)
#pragma unroll
            for (int r = 0; r < 4; r++) acc[mt][n8][r] = 0.f;

    int buf = 0;
    for (int s = 0; s < nst; s++) {
        const bool pf = (s + 1) < nst;
        uint4 av0, av1, bv0, bv1;
        if (pf) {
            int k0 = (s + 1) * 32;
            int rg = k0 / K;
            int kk = k0 - rg * K;
            const __nv_bfloat16* Ab = (rg == 1) ? a_lo : a_hi;
            const __nv_bfloat16* Bb = (rg == 2) ? b_lo : b_hi;
            uint4 z = make_uint4(0, 0, 0, 0);
            int gm = bm + id0_row;
            av0 = (gm < M) ? *(const uint4*)(Ab + (size_t)gm * K + kk + id0_c * 8) : z;
            gm = bm + id1_row;
            av1 = (gm < M) ? *(const uint4*)(Ab + (size_t)gm * K + kk + id1_c * 8) : z;
            int gn = bn + jd0_c * 8;
            bv0 = (gn < Nc) ? *(const uint4*)(Bb + (size_t)(kk + jd0_k) * Nc + gn) : z;
            gn = bn + jd1_c * 8;
            bv1 = (gn < Nc) ? *(const uint4*)(Bb + (size_t)(kk + jd1_k) * Nc + gn) : z;
        }

        const uint32_t abase = sptr(&As[buf][0]);
        const uint32_t bbase = sptr(&Bs[buf][0]);
#pragma unroll
        for (int h = 0; h < 2; h++) {
            uint32_t afr0[4], afr1[4];
            int arow = warp_m + (lane & 15);
            uint32_t ad0 = abase + (uint32_t)(arow * (A_PAD * 2) + h * 32 + (lane >> 4) * 16);
            uint32_t ad1 = ad0 + 16 * (A_PAD * 2);
            ldsm4(afr0, ad0);
            ldsm4(afr1, ad1);
#pragma unroll
            for (int nt = 0; nt < 4; nt++) {
                uint32_t bfr[4];
                uint32_t bd = bbase
                    + (uint32_t)((h * 16 + (lane & 15)) * (B_PAD * 2)
                    + (warp_n + nt * 16 + ((lane >> 4) << 3)) * 2);
                ldsm4t(bfr, bd);
                mma16816(acc[0][nt * 2],     afr0, bfr[0], bfr[1]);
                mma16816(acc[0][nt * 2 + 1], afr0, bfr[2], bfr[3]);
                mma16816(acc[1][nt * 2],     afr1, bfr[0], bfr[1]);
                mma16816(acc[1][nt * 2 + 1], afr1, bfr[2], bfr[3]);
            }
        }

        if (pf) {
            int nb = buf ^ 1;
            *(uint4*)(&As[nb][id0_row * A_PAD + id0_c * 8]) = av0;
            *(uint4*)(&As[nb][id1_row * A_PAD + id1_c * 8]) = av1;
            *(uint4*)(&Bs[nb][jd0_k * B_PAD + jd0_c * 8]) = bv0;
            *(uint4*)(&Bs[nb][jd1_k * B_PAD + jd1_c * 8]) = bv1;
        }
        __syncthreads();
        buf ^= 1;
    }

    // ---- epilogue (+ fused attention scores) ----
    float ss[2][2] = {{0.f, 0.f}, {0.f, 0.f}};
    float dd[2][2] = {{0.f, 0.f}, {0.f, 0.f}};
#pragma unroll
    for (int mt = 0; mt < 2; mt++) {
#pragma unroll
        for (int n8 = 0; n8 < 8; n8++) {
            int col = bn + warp_n + n8 * 8 + (lane & 3) * 2;
            if (col >= Nc) continue;
            float bb0 = 0.f, bb1 = 0.f;
            if (bias) { bb0 = bias[col]; bb1 = bias[col + 1]; }
            int row0 = bm + warp_m + mt * 16 + (lane >> 2);
            float v0 = acc[mt][n8][0] + bb0;
            float v1 = acc[mt][n8][1] + bb1;
            float v2 = acc[mt][n8][2] + bb0;
            float v3 = acc[mt][n8][3] + bb1;
            if (act) {
                v0 = fmaxf(v0, 0.f); v1 = fmaxf(v1, 0.f);
                v2 = fmaxf(v2, 0.f); v3 = fmaxf(v3, 0.f);
            }
            if (asrc) {
                float as0 = asrc[col], as1 = asrc[col + 1];
                float ad0 = adst[col], ad1 = adst[col + 1];
                ss[mt][0] += v0 * as0 + v1 * as1;
                ss[mt][1] += v2 * as0 + v3 * as1;
                dd[mt][0] += v0 * ad0 + v1 * ad1;
                dd[mt][1] += v2 * ad0 + v3 * ad1;
            }
            if (row0 < M) {
                size_t o = (size_t)row0 * Nc + col;
                if (Cf) {
                    float2 p; p.x = v0; p.y = v1;
                    *(float2*)&Cf[o] = p;
                } else {
                    __nv_bfloat16 h0 = __float2bfloat16(v0);
                    __nv_bfloat16 h1 = __float2bfloat16(v1);
                    __nv_bfloat162 hp; hp.x = h0; hp.y = h1;
                    *(__nv_bfloat162*)&c_hi[o] = hp;
                    __nv_bfloat162 lp;
                    lp.x = __float2bfloat16(v0 - __bfloat162float(h0));
                    lp.y = __float2bfloat16(v1 - __bfloat162float(h1));
                    *(__nv_bfloat162*)&c_lo[o] = lp;
                }
            }
            int row1 = row0 + 8;
            if (row1 < M) {
                size_t o = (size_t)row1 * Nc + col;
                if (Cf) {
                    float2 p; p.x = v2; p.y = v3;
                    *(float2*)&Cf[o] = p;
                } else {
                    __nv_bfloat16 h0 = __float2bfloat16(v2);
                    __nv_bfloat16 h1 = __float2bfloat16(v3);
                    __nv_bfloat162 hp; hp.x = h0; hp.y = h1;
                    *(__nv_bfloat162*)&c_hi[o] = hp;
                    __nv_bfloat162 lp;
                    lp.x = __float2bfloat16(v2 - __bfloat162float(h0));
                    lp.y = __float2bfloat16(v3 - __bfloat162float(h1));
                    *(__nv_bfloat162*)&c_lo[o] = lp;
                }
            }
        }
    }

    if (asrc && (bn + warp_n) < Nc) {
        int h = (bn + warp_n) >> 6;
#pragma unroll
        for (int mt = 0; mt < 2; mt++) {
#pragma unroll
            for (int r = 0; r < 2; r++) {
                float vs = ss[mt][r];
                float vd = dd[mt][r];
                vs += __shfl_xor_sync(0xffffffffu, vs, 1);
                vs += __shfl_xor_sync(0xffffffffu, vs, 2);
                vd += __shfl_xor_sync(0xffffffffu, vd, 1);
                vd += __shfl_xor_sync(0xffffffffu, vd, 2);
                int row = bm + warp_m + mt * 16 + (lane >> 2) + r * 8;
                if ((lane & 3) == 0 && row < M) {
                    ssrc[row * H + h] = vs;
                    sdst[row * H + h] = vd;
                }
            }
        }
    }
}

// ---------------- layer-1 agg: fused softmax-agg + bias + elu + bf16 split ----------------
__global__ void agg1_kernel(const float* __restrict__ xh,
                            const float* __restrict__ ssrc,
                            const float* __restrict__ sdst,
                            const float* __restrict__ bias,
                            __nv_bfloat16* __restrict__ ohi,
                            __nv_bfloat16* __restrict__ olo)
{
    int w = (blockIdx.x * blockDim.x + threadIdx.x) >> 5;
    int lane = threadIdx.x & 31;
    if (w >= NN * 4) return;
    int n = w >> 2, h = w & 3;
    int start = g_off[n], end = g_off[n + 1];
    float sd = sdst[n * 4 + h];
    float eself = lrelu(ssrc[n * 4 + h] + sd);

    float m = eself;
    for (int j = start + lane; j < end; j += 32)
        m = fmaxf(m, lrelu(ssrc[g_adj[j] * 4 + h] + sd));
#pragma unroll
    for (int o = 16; o; o >>= 1) m = fmaxf(m, __shfl_xor_sync(0xffffffffu, m, o));

    float wself = __expf(eself - m);
    float zpart = (lane == 0) ? wself : 0.f;
    const float* selfrow = xh + (size_t)n * 256 + h * 64;
    float a0 = wself * selfrow[lane],      b0 = 0.f;
    float a1 = wself * selfrow[lane + 32], b1 = 0.f;

    for (int j0 = start; j0 < end; j0 += 32) {
        int j = j0 + lane;
        int s = (j < end) ? g_adj[j] : n;
        float wv = 0.f;
        if (j < end) {
            wv = __expf(lrelu(ssrc[s * 4 + h] + sd) - m);
            zpart += wv;
        }
        int cnt = min(32, end - j0);
        int k = 0;
        for (; k + 1 < cnt; k += 2) {
            float wk0 = __shfl_sync(0xffffffffu, wv, k);
            int   sk0 = __shfl_sync(0xffffffffu, s, k);
            float wk1 = __shfl_sync(0xffffffffu, wv, k + 1);
            int   sk1 = __shfl_sync(0xffffffffu, s, k + 1);
            const float* r0 = xh + (size_t)sk0 * 256 + h * 64;
            const float* r1 = xh + (size_t)sk1 * 256 + h * 64;
            a0 = fmaf(wk0, r0[lane], a0);
            a1 = fmaf(wk0, r0[lane + 32], a1);
            b0 = fmaf(wk1, r1[lane], b0);
            b1 = fmaf(wk1, r1[lane + 32], b1);
        }
        if (k < cnt) {
            float wk = __shfl_sync(0xffffffffu, wv, k);
            int   sk = __shfl_sync(0xffffffffu, s, k);
            const float* r = xh + (size_t)sk * 256 + h * 64;
            a0 = fmaf(wk, r[lane], a0);
            a1 = fmaf(wk, r[lane + 32], a1);
        }
    }
#pragma unroll
    for (int o = 16; o; o >>= 1) zpart += __shfl_xor_sync(0xffffffffu, zpart, o);
    float inv = 1.f / zpart;
    float v0 = elu1((a0 + b0) * inv + bias[h * 64 + lane]);
    float v1 = elu1((a1 + b1) * inv + bias[h * 64 + lane + 32]);
    size_t o0 = (size_t)n * 256 + h * 64 + lane;
    __nv_bfloat16 h0 = __float2bfloat16(v0);
    __nv_bfloat16 h1 = __float2bfloat16(v1);
    ohi[o0]      = h0;
    ohi[o0 + 32] = h1;
    olo[o0]      = __float2bfloat16(v0 - __bfloat162float(h0));
    olo[o0 + 32] = __float2bfloat16(v1 - __bfloat162float(h1));
}

// ---------------- layer-2 agg: warp per node, BOTH heads + mean + bias + elu + split ----------------
__global__ void agg2_kernel(const float* __restrict__ xh,
                            const float* __restrict__ ssrc,
                            const float* __restrict__ sdst,
                            const float* __restrict__ bias,
                            __nv_bfloat16* __restrict__ ohi,
                            __nv_bfloat16* __restrict__ olo)
{
    int n = (blockIdx.x * blockDim.x + threadIdx.x) >> 5;
    int lane = threadIdx.x & 31;
    if (n >= NN) return;
    int start = g_off[n], end = g_off[n + 1];
    float sd0 = sdst[n * 2], sd1 = sdst[n * 2 + 1];
    float es0 = lrelu(ssrc[n * 2] + sd0);
    float es1 = lrelu(ssrc[n * 2 + 1] + sd1);

    float m0 = es0, m1 = es1;
    for (int j = start + lane; j < end; j += 32) {
        int s = g_adj[j];
        m0 = fmaxf(m0, lrelu(ssrc[s * 2] + sd0));
        m1 = fmaxf(m1, lrelu(ssrc[s * 2 + 1] + sd1));
    }
#pragma unroll
    for (int o = 16; o; o >>= 1) {
        m0 = fmaxf(m0, __shfl_xor_sync(0xffffffffu, m0, o));
        m1 = fmaxf(m1, __shfl_xor_sync(0xffffffffu, m1, o));
    }

    float ws0 = __expf(es0 - m0), ws1 = __expf(es1 - m1);
    float z0 = (lane == 0) ? ws0 : 0.f;
    float z1 = (lane == 0) ? ws1 : 0.f;
    const float* selfrow = xh + (size_t)n * 128;
    float a00 = ws0 * selfrow[lane],      a01 = ws0 * selfrow[lane + 32];
    float a10 = ws1 * selfrow[lane + 64], a11 = ws1 * selfrow[lane + 96];

    for (int j0 = start; j0 < end; j0 += 32) {
        int j = j0 + lane;
        int s = (j < end) ? g_adj[j] : n;
        float w0 = 0.f, w1 = 0.f;
        if (j < end) {
            w0 = __expf(lrelu(ssrc[s * 2] + sd0) - m0);
            w1 = __expf(lrelu(ssrc[s * 2 + 1] + sd1) - m1);
            z0 += w0; z1 += w1;
        }
        int cnt = min(32, end - j0);
        for (int k = 0; k < cnt; k++) {
            float wk0 = __shfl_sync(0xffffffffu, w0, k);
            float wk1 = __shfl_sync(0xffffffffu, w1, k);
            int   sk  = __shfl_sync(0xffffffffu, s, k);
            const float* r = xh + (size_t)sk * 128;
            a00 = fmaf(wk0, r[lane], a00);
            a01 = fmaf(wk0, r[lane + 32], a01);
            a10 = fmaf(wk1, r[lane + 64], a10);
            a11 = fmaf(wk1, r[lane + 96], a11);
        }
    }
#pragma unroll
    for (int o = 16; o; o >>= 1) {
        z0 += __shfl_xor_sync(0xffffffffu, z0, o);
        z1 += __shfl_xor_sync(0xffffffffu, z1, o);
    }
    float i0 = 1.f / z0, i1 = 1.f / z1;
    float v0 = elu1(0.5f * (a00 * i0 + a10 * i1) + bias[lane]);
    float v1 = elu1(0.5f * (a01 * i0 + a11 * i1) + bias[lane + 32]);
    size_t o0 = (size_t)n * 64 + lane;
    __nv_bfloat16 h0 = __float2bfloat16(v0);
    __nv_bfloat16 h1 = __float2bfloat16(v1);
    ohi[o0]      = h0;
    ohi[o0 + 32] = h1;
    olo[o0]      = __float2bfloat16(v0 - __bfloat162float(h0));
    olo[o0 + 32] = __float2bfloat16(v1 - __bfloat162float(h1));
}

// ---------------- layer-3 agg: warp per node, H=1, + bias -> d_out ----------------
__global__ void agg3_kernel(const float* __restrict__ xh,
                            const float* __restrict__ ssrc,
                            const float* __restrict__ sdst,
                            const float* __restrict__ bias,
                            float* __restrict__ out)
{
    int n = (blockIdx.x * blockDim.x + threadIdx.x) >> 5;
    int lane = threadIdx.x & 31;
    if (n >= NN) return;
    int start = g_off[n], end = g_off[n + 1];
    float sd = sdst[n];
    float eself = lrelu(ssrc[n] + sd);

    float m = eself;
    for (int j = start + lane; j < end; j += 32)
        m = fmaxf(m, lrelu(ssrc[g_adj[j]] + sd));
#pragma unroll
    for (int o = 16; o; o >>= 1) m = fmaxf(m, __shfl_xor_sync(0xffffffffu, m, o));

    float wself = __expf(eself - m);
    float zpart = (lane == 0) ? wself : 0.f;
    const float* selfrow = xh + (size_t)n * 64;
    float a0 = wself * selfrow[lane],      b0 = 0.f;
    float a1 = wself * selfrow[lane + 32], b1 = 0.f;

    for (int j0 = start; j0 < end; j0 += 32) {
        int j = j0 + lane;
        int s = (j < end) ? g_adj[j] : n;
        float wv = 0.f;
        if (j < end) {
            wv = __expf(lrelu(ssrc[s] + sd) - m);
            zpart += wv;
        }
        int cnt = min(32, end - j0);
        int k = 0;
        for (; k + 1 < cnt; k += 2) {
            float wk0 = __shfl_sync(0xffffffffu, wv, k);
            int   sk0 = __shfl_sync(0xffffffffu, s, k);
            float wk1 = __shfl_sync(0xffffffffu, wv, k + 1);
            int   sk1 = __shfl_sync(0xffffffffu, s, k + 1);
            const float* r0 = xh + (size_t)sk0 * 64;
            const float* r1 = xh + (size_t)sk1 * 64;
            a0 = fmaf(wk0, r0[lane], a0);
            a1 = fmaf(wk0, r0[lane + 32], a1);
            b0 = fmaf(wk1, r1[lane], b0);
            b1 = fmaf(wk1, r1[lane + 32], b1);
        }
        if (k < cnt) {
            float wk = __shfl_sync(0xffffffffu, wv, k);
            int   sk = __shfl_sync(0xffffffffu, s, k);
            const float* r = xh + (size_t)sk * 64;
            a0 = fmaf(wk, r[lane], a0);
            a1 = fmaf(wk, r[lane + 32], a1);
        }
    }
#pragma unroll
    for (int o = 16; o; o >>= 1) zpart += __shfl_xor_sync(0xffffffffu, zpart, o);
    float inv = 1.f / zpart;
    out[(size_t)n * 64 + lane]      = (a0 + b0) * inv + bias[lane];
    out[(size_t)n * 64 + lane + 32] = (a1 + b1) * inv + bias[lane + 32];
}

// ---------------- host ----------------
extern "C" void kernel_launch(void* const* d_in, const int* in_sizes, int n_in,
                              void* d_out, int out_size) {
    const float* x     = (const float*)d_in[0];
    const int*   ei    = (const int*)  d_in[1];
    const float* w1    = (const float*)d_in[2];
    const float* b1    = (const float*)d_in[3];
    const float* w2    = (const float*)d_in[4];
    const float* b2    = (const float*)d_in[5];
    const float* g1w   = (const float*)d_in[6];
    const float* g1as  = (const float*)d_in[7];
    const float* g1ad  = (const float*)d_in[8];
    const float* g1b   = (const float*)d_in[9];
    const float* g2w   = (const float*)d_in[10];
    const float* g2as  = (const float*)d_in[11];
    const float* g2ad  = (const float*)d_in[12];
    const float* g2b   = (const float*)d_in[13];
    const float* g3w   = (const float*)d_in[14];
    const float* g3as  = (const float*)d_in[15];
    const float* g3ad  = (const float*)d_in[16];
    const float* g3b   = (const float*)d_in[17];

    int E = in_sizes[1] / 2;
    if (E > EMAX) E = EMAX;
    const int* srcp = ei;
    const int* dstp = ei + E;

    float *xh, *ssrc, *sdst;
    int *deg, *cur;
    __nv_bfloat16 *Phi, *Plo, *Qhi, *Qlo, *whi, *wlo;
    cudaGetSymbolAddress((void**)&xh,   g_xh);
    cudaGetSymbolAddress((void**)&ssrc, g_ssrc);
    cudaGetSymbolAddress((void**)&sdst, g_sdst);
    cudaGetSymbolAddress((void**)&deg,  g_deg);
    cudaGetSymbolAddress((void**)&cur,  g_cur);
    cudaGetSymbolAddress((void**)&Phi,  g_Phi);
    cudaGetSymbolAddress((void**)&Plo,  g_Plo);
    cudaGetSymbolAddress((void**)&Qhi,  g_Qhi);
    cudaGetSymbolAddress((void**)&Qlo,  g_Qlo);
    cudaGetSymbolAddress((void**)&whi,  g_whi);
    cudaGetSymbolAddress((void**)&wlo,  g_wlo);

    const int OW1 = 0, OW2 = 32768, OG1 = 49152, OG2 = 81920, OG3 = 114688;
    const int GY = (NN + 127) / 128;   // 391

    // ---- launches 1-5: memsets + first splits (launch #6 = big tgemm for ncu) ----
    cudaMemsetAsync(deg, 0, NN * sizeof(int));
    cudaMemsetAsync(cur, 0, NN * sizeof(int));
    {
        int n4 = NN * 256 / 4;
        split4_kernel<<<(n4 + 255) / 256, 256>>>((const float4*)x, (__nv_bfloat162*)Phi, (__nv_bfloat162*)Plo, n4);
        split4_kernel<<<(32768/4 + 255) / 256, 256>>>((const float4*)w1,  (__nv_bfloat162*)(whi + OW1), (__nv_bfloat162*)(wlo + OW1), 32768/4);
        split4_kernel<<<(16384/4 + 255) / 256, 256>>>((const float4*)w2,  (__nv_bfloat162*)(whi + OW2), (__nv_bfloat162*)(wlo + OW2), 16384/4);
    }

    // ---- launch #6: MLP GEMM 1 (profiled) ----
    tgemm_kernel<<<dim3(1, GY), 256>>>(Phi, Plo, whi + OW1, wlo + OW1, b1, nullptr, Qhi, Qlo,
                                       nullptr, nullptr, nullptr, nullptr, 0, NN, 256, 128, 1);

    // ---- remaining splits + CSR build ----
    split4_kernel<<<(32768/4 + 255) / 256, 256>>>((const float4*)g1w, (__nv_bfloat162*)(whi + OG1), (__nv_bfloat162*)(wlo + OG1), 32768/4);
    split4_kernel<<<(32768/4 + 255) / 256, 256>>>((const float4*)g2w, (__nv_bfloat162*)(whi + OG2), (__nv_bfloat162*)(wlo + OG2), 32768/4);
    split4_kernel<<<(4096/4 + 255) / 256, 256>>>((const float4*)g3w,  (__nv_bfloat162*)(whi + OG3), (__nv_bfloat162*)(wlo + OG3), 4096/4);
    deg_kernel<<<(E + 255) / 256, 256>>>(dstp, E);
    scan_kernel<<<1, 1024>>>(NN);
    scatter_kernel<<<(E + 255) / 256, 256>>>(srcp, dstp, E);

    // ---- MLP GEMM 2 ----
    tgemm_kernel<<<dim3(1, GY), 256>>>(Qhi, Qlo, whi + OW2, wlo + OW2, b2, nullptr, Phi, Plo,
                                       nullptr, nullptr, nullptr, nullptr, 0, NN, 128, 128, 1);

    // ---- GAT 1 (scores fused in GEMM; agg fused with bias+elu+split) ----
    tgemm_kernel<<<dim3(2, GY), 256>>>(Phi, Plo, whi + OG1, wlo + OG1, nullptr, xh, nullptr, nullptr,
                                       g1as, g1ad, ssrc, sdst, 4, NN, 128, 256, 0);
    agg1_kernel<<<(NN * 4 * 32 + 255) / 256, 256>>>(xh, ssrc, sdst, g1b, Qhi, Qlo);

    // ---- GAT 2 ----
    tgemm_kernel<<<dim3(1, GY), 256>>>(Qhi, Qlo, whi + OG2, wlo + OG2, nullptr, xh, nullptr, nullptr,
                                       g2as, g2ad, ssrc, sdst, 2, NN, 256, 128, 0);
    agg2_kernel<<<(NN * 32 + 255) / 256, 256>>>(xh, ssrc, sdst, g2b, Phi, Plo);

    // ---- GAT 3 ----
    tgemm_kernel<<<dim3(1, GY), 256>>>(Phi, Plo, whi + OG3, wlo + OG3, nullptr, xh, nullptr, nullptr,
                                       g3as, g3ad, ssrc, sdst, 1, NN, 64, 64, 0);
    agg3_kernel<<<(NN * 32 + 255) / 256, 256>>>(xh, ssrc, sdst, g3b, (float*)d_out);
}

// round 17
// speedup vs baseline: 1.5676x; 1.0371x over previous
#include <cuda_runtime.h>
#include <cuda_bf16.h>
#include <cstdint>
#include <cstddef>

#define NN 50000
#define EMAX 800000

// ---------------- scratch (device globals; no allocation allowed) ----------------
__device__ float g_xh[(size_t)NN * 256];
__device__ float g_ssrc[NN * 4];
__device__ float g_sdst[NN * 4];
__device__ int   g_off[NN + 1];
__device__ int   g_deg[NN];
__device__ int   g_cur[NN];
__device__ int   g_adj[EMAX];

// split bf16 buffers
__device__ __align__(16) __nv_bfloat16 g_Phi[(size_t)NN * 256];
__device__ __align__(16) __nv_bfloat16 g_Plo[(size_t)NN * 256];
__device__ __align__(16) __nv_bfloat16 g_Qhi[(size_t)NN * 256];
__device__ __align__(16) __nv_bfloat16 g_Qlo[(size_t)NN * 256];
__device__ __align__(16) __nv_bfloat16 g_whi[131072];
__device__ __align__(16) __nv_bfloat16 g_wlo[131072];

__device__ __forceinline__ float lrelu(float x) { return fmaxf(x, 0.2f * x); }
__device__ __forceinline__ float elu1(float x)  { return x > 0.f ? x : expm1f(x); }

// ---------------- CSR build ----------------
__global__ void deg_kernel(const int* __restrict__ dst, int E) {
    int i = blockIdx.x * blockDim.x + threadIdx.x;
    if (i < E) atomicAdd(&g_deg[dst[i]], 1);
}

__global__ void scan_kernel(int n) {
    __shared__ int s[1024];
    int tid = threadIdx.x;
    const int chunk = (n + 1023) / 1024;
    int begin = tid * chunk;
    int endi  = min(begin + chunk, n);
    int sum = 0;
    for (int i = begin; i < endi; i++) sum += g_deg[i];
    s[tid] = sum;
    __syncthreads();
    for (int off = 1; off < 1024; off <<= 1) {
        int v = (tid >= off) ? s[tid - off] : 0;
        __syncthreads();
        s[tid] += v;
        __syncthreads();
    }
    int run = (tid == 0) ? 0 : s[tid - 1];
    for (int i = begin; i < endi; i++) { g_off[i] = run; run += g_deg[i]; }
    if (tid == 1023) g_off[n] = s[1023];
}

__global__ void scatter_kernel(const int* __restrict__ src, const int* __restrict__ dst, int E) {
    int i = blockIdx.x * blockDim.x + threadIdx.x;
    if (i < E) {
        int d = dst[i];
        int pos = g_off[d] + atomicAdd(&g_cur[d], 1);
        g_adj[pos] = src[i];
    }
}

// ---------------- vectorized fp32 -> bf16 hi/lo split ----------------
__global__ void split4_kernel(const float4* __restrict__ a,
                              __nv_bfloat162* __restrict__ hi,
                              __nv_bfloat162* __restrict__ lo, int n4) {
    int i = blockIdx.x * blockDim.x + threadIdx.x;
    if (i < n4) {
        float4 f = a[i];
        __nv_bfloat16 h0 = __float2bfloat16(f.x);
        __nv_bfloat16 h1 = __float2bfloat16(f.y);
        __nv_bfloat16 h2 = __float2bfloat16(f.z);
        __nv_bfloat16 h3 = __float2bfloat16(f.w);
        __nv_bfloat162 a0; a0.x = h0; a0.y = h1;
        __nv_bfloat162 a1; a1.x = h2; a1.y = h3;
        hi[i * 2]     = a0;
        hi[i * 2 + 1] = a1;
        __nv_bfloat162 l0, l1;
        l0.x = __float2bfloat16(f.x - __bfloat162float(h0));
        l0.y = __float2bfloat16(f.y - __bfloat162float(h1));
        l1.x = __float2bfloat16(f.z - __bfloat162float(h2));
        l1.y = __float2bfloat16(f.w - __bfloat162float(h3));
        lo[i * 2]     = l0;
        lo[i * 2 + 1] = l1;
    }
}

// ---------------- tensor-core GEMM: cp.async pipeline + fragment pipelining ----------------
__device__ __forceinline__ uint32_t sptr(const void* p) {
    return (uint32_t)__cvta_generic_to_shared(p);
}
__device__ __forceinline__ void ldsm4(uint32_t* r, uint32_t a) {
    asm volatile("ldmatrix.sync.aligned.m8n8.x4.shared.b16 {%0,%1,%2,%3},[%4];\n"
                 : "=r"(r[0]), "=r"(r[1]), "=r"(r[2]), "=r"(r[3]) : "r"(a));
}
__device__ __forceinline__ void ldsm4t(uint32_t* r, uint32_t a) {
    asm volatile("ldmatrix.sync.aligned.m8n8.x4.trans.shared.b16 {%0,%1,%2,%3},[%4];\n"
                 : "=r"(r[0]), "=r"(r[1]), "=r"(r[2]), "=r"(r[3]) : "r"(a));
}
__device__ __forceinline__ void mma16816(float* d, const uint32_t* a, uint32_t b0, uint32_t b1) {
    asm volatile("mma.sync.aligned.m16n8k16.row.col.f32.bf16.bf16.f32 "
                 "{%0,%1,%2,%3},{%4,%5,%6,%7},{%8,%9},{%0,%1,%2,%3};\n"
                 : "+f"(d[0]), "+f"(d[1]), "+f"(d[2]), "+f"(d[3])
                 : "r"(a[0]), "r"(a[1]), "r"(a[2]), "r"(a[3]), "r"(b0), "r"(b1));
}
__device__ __forceinline__ void cpasync16(uint32_t dst, const void* src, int sz) {
    asm volatile("cp.async.cg.shared.global [%0], [%1], 16, %2;\n"
                 :: "r"(dst), "l"(src), "r"(sz));
}
#define CP_COMMIT() asm volatile("cp.async.commit_group;\n" ::: "memory")
#define CP_WAIT0()  asm volatile("cp.async.wait_group 0;\n" ::: "memory")

#define A_PAD 40
#define B_PAD 136

__global__ __launch_bounds__(256, 2) void tgemm_kernel(
    const __nv_bfloat16* __restrict__ a_hi, const __nv_bfloat16* __restrict__ a_lo,
    const __nv_bfloat16* __restrict__ b_hi, const __nv_bfloat16* __restrict__ b_lo,
    const float* __restrict__ bias,
    float* __restrict__ Cf,
    __nv_bfloat16* __restrict__ c_hi, __nv_bfloat16* __restrict__ c_lo,
    const float* __restrict__ asrc, const float* __restrict__ adst,
    float* __restrict__ ssrc, float* __restrict__ sdst, int H,
    int M, int K, int Nc, int act)
{
    __shared__ __align__(16) __nv_bfloat16 As[2][128 * A_PAD];
    __shared__ __align__(16) __nv_bfloat16 Bs[2][32 * B_PAD];

    const int tid  = threadIdx.x;
    const int wid  = tid >> 5;
    const int lane = tid & 31;
    const int warp_m = (wid & 3) * 32;
    const int warp_n = (wid >> 2) * 64;
    const int bm = blockIdx.y * 128;
    const int bn = blockIdx.x * 128;

    const int id0_row = tid >> 2,          id0_c = tid & 3;
    const int id1_row = (tid + 256) >> 2,  id1_c = tid & 3;
    const int jd0_k   = tid >> 4,          jd0_c = tid & 15;
    const int jd1_k   = (tid + 256) >> 4,  jd1_c = tid & 15;

    const int nst = (3 * K) >> 5;

    const uint32_t abufsz = (uint32_t)(128 * A_PAD * 2);
    const uint32_t bbufsz = (uint32_t)(32 * B_PAD * 2);
    const uint32_t a_s0 = sptr(&As[0][id0_row * A_PAD + id0_c * 8]);
    const uint32_t a_s1 = sptr(&As[0][id1_row * A_PAD + id1_c * 8]);
    const uint32_t b_s0 = sptr(&Bs[0][jd0_k * B_PAD + jd0_c * 8]);
    const uint32_t b_s1 = sptr(&Bs[0][jd1_k * B_PAD + jd1_c * 8]);

    const int gm0 = bm + id0_row, gm1 = bm + id1_row;
    const int gn0 = bn + jd0_c * 8, gn1 = bn + jd1_c * 8;
    const int za0 = (gm0 < M) ? 16 : 0;
    const int za1 = (gm1 < M) ? 16 : 0;
    const int zb0 = (gn0 < Nc) ? 16 : 0;
    const int zb1 = (gn1 < Nc) ? 16 : 0;

    // issue one stage's cp.async into buffer b
    auto issue_stage = [&](int s, int b) {
        int k0 = s * 32;
        int rg = k0 / K;
        int kk = k0 - rg * K;
        const __nv_bfloat16* Ab = (rg == 1) ? a_lo : a_hi;
        const __nv_bfloat16* Bb = (rg == 2) ? b_lo : b_hi;
        cpasync16(a_s0 + b * abufsz, Ab + (size_t)gm0 * K + kk + id0_c * 8, za0);
        cpasync16(a_s1 + b * abufsz, Ab + (size_t)gm1 * K + kk + id1_c * 8, za1);
        cpasync16(b_s0 + b * bbufsz, Bb + (size_t)(kk + jd0_k) * Nc + gn0, zb0);
        cpasync16(b_s1 + b * bbufsz, Bb + (size_t)(kk + jd1_k) * Nc + gn1, zb1);
        CP_COMMIT();
    };

    issue_stage(0, 0);

    float acc[2][8][4];
#pragma unroll
    for (int mt = 0; mt < 2; mt++)
#pragma unroll
        for (int n8 = 0; n8 < 8; n8++)
#pragma unroll
            for (int r = 0; r < 4; r++) acc[mt][n8][r] = 0.f;

    CP_WAIT0();
    __syncthreads();

    const int arow = warp_m + (lane & 15);
    const uint32_t a_off = (uint32_t)(arow * (A_PAD * 2) + (lane >> 4) * 16);
    const uint32_t b_off0 = (uint32_t)((lane & 15) * (B_PAD * 2)
                         + (warp_n + ((lane >> 4) << 3)) * 2);

    int buf = 0;
    for (int s = 0; s < nst; s++) {
        const bool pf = (s + 1) < nst;
        if (pf) issue_stage(s + 1, buf ^ 1);

        const uint32_t abase = sptr(&As[buf][0]);
        const uint32_t bbase = sptr(&Bs[buf][0]);

        // hoist all A fragments for this stage
        uint32_t afr[2][2][4];
#pragma unroll
        for (int h = 0; h < 2; h++) {
            uint32_t ad0 = abase + a_off + h * 32;
            ldsm4(afr[h][0], ad0);
            ldsm4(afr[h][1], ad0 + 16 * (A_PAD * 2));
        }

        // B fragments double-buffered: ldsm one group ahead of its mmas
        uint32_t bfr[2][4];
        ldsm4t(bfr[0], bbase + b_off0);
        int pb = 0;
#pragma unroll
        for (int h = 0; h < 2; h++) {
#pragma unroll
            for (int nt = 0; nt < 4; nt++) {
                int idx = h * 4 + nt;
                if (idx < 7) {
                    int nidx = idx + 1;
                    int nh = nidx >> 2, nn = nidx & 3;
                    ldsm4t(bfr[pb ^ 1], bbase + b_off0
                           + (uint32_t)(nh * 16 * (B_PAD * 2) + nn * 16 * 2));
                }
                mma16816(acc[0][nt * 2],     afr[h][0], bfr[pb][0], bfr[pb][1]);
                mma16816(acc[0][nt * 2 + 1], afr[h][0], bfr[pb][2], bfr[pb][3]);
                mma16816(acc[1][nt * 2],     afr[h][1], bfr[pb][0], bfr[pb][1]);
                mma16816(acc[1][nt * 2 + 1], afr[h][1], bfr[pb][2], bfr[pb][3]);
                pb ^= 1;
            }
        }

        if (pf) {
            CP_WAIT0();
            __syncthreads();
        }
        buf ^= 1;
    }

    // ---- epilogue (+ fused attention scores) ----
    float ss[2][2] = {{0.f, 0.f}, {0.f, 0.f}};
    float dd[2][2] = {{0.f, 0.f}, {0.f, 0.f}};
#pragma unroll
    for (int mt = 0; mt < 2; mt++) {
#pragma unroll
        for (int n8 = 0; n8 < 8; n8++) {
            int col = bn + warp_n + n8 * 8 + (lane & 3) * 2;
            if (col >= Nc) continue;
            float bb0 = 0.f, bb1 = 0.f;
            if (bias) { bb0 = bias[col]; bb1 = bias[col + 1]; }
            int row0 = bm + warp_m + mt * 16 + (lane >> 2);
            float v0 = acc[mt][n8][0] + bb0;
            float v1 = acc[mt][n8][1] + bb1;
            float v2 = acc[mt][n8][2] + bb0;
            float v3 = acc[mt][n8][3] + bb1;
            if (act) {
                v0 = fmaxf(v0, 0.f); v1 = fmaxf(v1, 0.f);
                v2 = fmaxf(v2, 0.f); v3 = fmaxf(v3, 0.f);
            }
            if (asrc) {
                float as0 = asrc[col], as1 = asrc[col + 1];
                float ad0 = adst[col], ad1 = adst[col + 1];
                ss[mt][0] += v0 * as0 + v1 * as1;
                ss[mt][1] += v2 * as0 + v3 * as1;
                dd[mt][0] += v0 * ad0 + v1 * ad1;
                dd[mt][1] += v2 * ad0 + v3 * ad1;
            }
            if (row0 < M) {
                size_t o = (size_t)row0 * Nc + col;
                if (Cf) {
                    float2 p; p.x = v0; p.y = v1;
                    *(float2*)&Cf[o] = p;
                } else {
                    __nv_bfloat16 h0 = __float2bfloat16(v0);
                    __nv_bfloat16 h1 = __float2bfloat16(v1);
                    __nv_bfloat162 hp; hp.x = h0; hp.y = h1;
                    *(__nv_bfloat162*)&c_hi[o] = hp;
                    __nv_bfloat162 lp;
                    lp.x = __float2bfloat16(v0 - __bfloat162float(h0));
                    lp.y = __float2bfloat16(v1 - __bfloat162float(h1));
                    *(__nv_bfloat162*)&c_lo[o] = lp;
                }
            }
            int row1 = row0 + 8;
            if (row1 < M) {
                size_t o = (size_t)row1 * Nc + col;
                if (Cf) {
                    float2 p; p.x = v2; p.y = v3;
                    *(float2*)&Cf[o] = p;
                } else {
                    __nv_bfloat16 h0 = __float2bfloat16(v2);
                    __nv_bfloat16 h1 = __float2bfloat16(v3);
                    __nv_bfloat162 hp; hp.x = h0; hp.y = h1;
                    *(__nv_bfloat162*)&c_hi[o] = hp;
                    __nv_bfloat162 lp;
                    lp.x = __float2bfloat16(v2 - __bfloat162float(h0));
                    lp.y = __float2bfloat16(v3 - __bfloat162float(h1));
                    *(__nv_bfloat162*)&c_lo[o] = lp;
                }
            }
        }
    }

    if (asrc && (bn + warp_n) < Nc) {
        int h = (bn + warp_n) >> 6;
#pragma unroll
        for (int mt = 0; mt < 2; mt++) {
#pragma unroll
            for (int r = 0; r < 2; r++) {
                float vs = ss[mt][r];
                float vd = dd[mt][r];
                vs += __shfl_xor_sync(0xffffffffu, vs, 1);
                vs += __shfl_xor_sync(0xffffffffu, vs, 2);
                vd += __shfl_xor_sync(0xffffffffu, vd, 1);
                vd += __shfl_xor_sync(0xffffffffu, vd, 2);
                int row = bm + warp_m + mt * 16 + (lane >> 2) + r * 8;
                if ((lane & 3) == 0 && row < M) {
                    ssrc[row * H + h] = vs;
                    sdst[row * H + h] = vd;
                }
            }
        }
    }
}

// ---------------- layer-1 agg: fused softmax-agg + bias + elu + bf16 split ----------------
__global__ void agg1_kernel(const float* __restrict__ xh,
                            const float* __restrict__ ssrc,
                            const float* __restrict__ sdst,
                            const float* __restrict__ bias,
                            __nv_bfloat16* __restrict__ ohi,
                            __nv_bfloat16* __restrict__ olo)
{
    int w = (blockIdx.x * blockDim.x + threadIdx.x) >> 5;
    int lane = threadIdx.x & 31;
    if (w >= NN * 4) return;
    int n = w >> 2, h = w & 3;
    int start = g_off[n], end = g_off[n + 1];
    float sd = sdst[n * 4 + h];
    float eself = lrelu(ssrc[n * 4 + h] + sd);

    float m = eself;
    for (int j = start + lane; j < end; j += 32)
        m = fmaxf(m, lrelu(ssrc[g_adj[j] * 4 + h] + sd));
#pragma unroll
    for (int o = 16; o; o >>= 1) m = fmaxf(m, __shfl_xor_sync(0xffffffffu, m, o));

    float wself = __expf(eself - m);
    float zpart = (lane == 0) ? wself : 0.f;
    const float* selfrow = xh + (size_t)n * 256 + h * 64;
    float a0 = wself * selfrow[lane],      b0 = 0.f;
    float a1 = wself * selfrow[lane + 32], b1 = 0.f;

    for (int j0 = start; j0 < end; j0 += 32) {
        int j = j0 + lane;
        int s = (j < end) ? g_adj[j] : n;
        float wv = 0.f;
        if (j < end) {
            wv = __expf(lrelu(ssrc[s * 4 + h] + sd) - m);
            zpart += wv;
        }
        int cnt = min(32, end - j0);
        int k = 0;
        for (; k + 1 < cnt; k += 2) {
            float wk0 = __shfl_sync(0xffffffffu, wv, k);
            int   sk0 = __shfl_sync(0xffffffffu, s, k);
            float wk1 = __shfl_sync(0xffffffffu, wv, k + 1);
            int   sk1 = __shfl_sync(0xffffffffu, s, k + 1);
            const float* r0 = xh + (size_t)sk0 * 256 + h * 64;
            const float* r1 = xh + (size_t)sk1 * 256 + h * 64;
            a0 = fmaf(wk0, r0[lane], a0);
            a1 = fmaf(wk0, r0[lane + 32], a1);
            b0 = fmaf(wk1, r1[lane], b0);
            b1 = fmaf(wk1, r1[lane + 32], b1);
        }
        if (k < cnt) {
            float wk = __shfl_sync(0xffffffffu, wv, k);
            int   sk = __shfl_sync(0xffffffffu, s, k);
            const float* r = xh + (size_t)sk * 256 + h * 64;
            a0 = fmaf(wk, r[lane], a0);
            a1 = fmaf(wk, r[lane + 32], a1);
        }
    }
#pragma unroll
    for (int o = 16; o; o >>= 1) zpart += __shfl_xor_sync(0xffffffffu, zpart, o);
    float inv = 1.f / zpart;
    float v0 = elu1((a0 + b0) * inv + bias[h * 64 + lane]);
    float v1 = elu1((a1 + b1) * inv + bias[h * 64 + lane + 32]);
    size_t o0 = (size_t)n * 256 + h * 64 + lane;
    __nv_bfloat16 h0 = __float2bfloat16(v0);
    __nv_bfloat16 h1 = __float2bfloat16(v1);
    ohi[o0]      = h0;
    ohi[o0 + 32] = h1;
    olo[o0]      = __float2bfloat16(v0 - __bfloat162float(h0));
    olo[o0 + 32] = __float2bfloat16(v1 - __bfloat162float(h1));
}

// ---------------- layer-2 agg: warp per node, BOTH heads + mean + bias + elu + split ----------------
__global__ void agg2_kernel(const float* __restrict__ xh,
                            const float* __restrict__ ssrc,
                            const float* __restrict__ sdst,
                            const float* __restrict__ bias,
                            __nv_bfloat16* __restrict__ ohi,
                            __nv_bfloat16* __restrict__ olo)
{
    int n = (blockIdx.x * blockDim.x + threadIdx.x) >> 5;
    int lane = threadIdx.x & 31;
    if (n >= NN) return;
    int start = g_off[n], end = g_off[n + 1];
    float sd0 = sdst[n * 2], sd1 = sdst[n * 2 + 1];
    float es0 = lrelu(ssrc[n * 2] + sd0);
    float es1 = lrelu(ssrc[n * 2 + 1] + sd1);

    float m0 = es0, m1 = es1;
    for (int j = start + lane; j < end; j += 32) {
        int s = g_adj[j];
        m0 = fmaxf(m0, lrelu(ssrc[s * 2] + sd0));
        m1 = fmaxf(m1, lrelu(ssrc[s * 2 + 1] + sd1));
    }
#pragma unroll
    for (int o = 16; o; o >>= 1) {
        m0 = fmaxf(m0, __shfl_xor_sync(0xffffffffu, m0, o));
        m1 = fmaxf(m1, __shfl_xor_sync(0xffffffffu, m1, o));
    }

    float ws0 = __expf(es0 - m0), ws1 = __expf(es1 - m1);
    float z0 = (lane == 0) ? ws0 : 0.f;
    float z1 = (lane == 0) ? ws1 : 0.f;
    const float* selfrow = xh + (size_t)n * 128;
    float a00 = ws0 * selfrow[lane],      a01 = ws0 * selfrow[lane + 32];
    float a10 = ws1 * selfrow[lane + 64], a11 = ws1 * selfrow[lane + 96];

    for (int j0 = start; j0 < end; j0 += 32) {
        int j = j0 + lane;
        int s = (j < end) ? g_adj[j] : n;
        float w0 = 0.f, w1 = 0.f;
        if (j < end) {
            w0 = __expf(lrelu(ssrc[s * 2] + sd0) - m0);
            w1 = __expf(lrelu(ssrc[s * 2 + 1] + sd1) - m1);
            z0 += w0; z1 += w1;
        }
        int cnt = min(32, end - j0);
        for (int k = 0; k < cnt; k++) {
            float wk0 = __shfl_sync(0xffffffffu, w0, k);
            float wk1 = __shfl_sync(0xffffffffu, w1, k);
            int   sk  = __shfl_sync(0xffffffffu, s, k);
            const float* r = xh + (size_t)sk * 128;
            a00 = fmaf(wk0, r[lane], a00);
            a01 = fmaf(wk0, r[lane + 32], a01);
            a10 = fmaf(wk1, r[lane + 64], a10);
            a11 = fmaf(wk1, r[lane + 96], a11);
        }
    }
#pragma unroll
    for (int o = 16; o; o >>= 1) {
        z0 += __shfl_xor_sync(0xffffffffu, z0, o);
        z1 += __shfl_xor_sync(0xffffffffu, z1, o);
    }
    float i0 = 1.f / z0, i1 = 1.f / z1;
    float v0 = elu1(0.5f * (a00 * i0 + a10 * i1) + bias[lane]);
    float v1 = elu1(0.5f * (a01 * i0 + a11 * i1) + bias[lane + 32]);
    size_t o0 = (size_t)n * 64 + lane;
    __nv_bfloat16 h0 = __float2bfloat16(v0);
    __nv_bfloat16 h1 = __float2bfloat16(v1);
    ohi[o0]      = h0;
    ohi[o0 + 32] = h1;
    olo[o0]      = __float2bfloat16(v0 - __bfloat162float(h0));
    olo[o0 + 32] = __float2bfloat16(v1 - __bfloat162float(h1));
}

// ---------------- layer-3 agg: warp per node, H=1, + bias -> d_out ----------------
__global__ void agg3_kernel(const float* __restrict__ xh,
                            const float* __restrict__ ssrc,
                            const float* __restrict__ sdst,
                            const float* __restrict__ bias,
                            float* __restrict__ out)
{
    int n = (blockIdx.x * blockDim.x + threadIdx.x) >> 5;
    int lane = threadIdx.x & 31;
    if (n >= NN) return;
    int start = g_off[n], end = g_off[n + 1];
    float sd = sdst[n];
    float eself = lrelu(ssrc[n] + sd);

    float m = eself;
    for (int j = start + lane; j < end; j += 32)
        m = fmaxf(m, lrelu(ssrc[g_adj[j]] + sd));
#pragma unroll
    for (int o = 16; o; o >>= 1) m = fmaxf(m, __shfl_xor_sync(0xffffffffu, m, o));

    float wself = __expf(eself - m);
    float zpart = (lane == 0) ? wself : 0.f;
    const float* selfrow = xh + (size_t)n * 64;
    float a0 = wself * selfrow[lane],      b0 = 0.f;
    float a1 = wself * selfrow[lane + 32], b1 = 0.f;

    for (int j0 = start; j0 < end; j0 += 32) {
        int j = j0 + lane;
        int s = (j < end) ? g_adj[j] : n;
        float wv = 0.f;
        if (j < end) {
            wv = __expf(lrelu(ssrc[s] + sd) - m);
            zpart += wv;
        }
        int cnt = min(32, end - j0);
        int k = 0;
        for (; k + 1 < cnt; k += 2) {
            float wk0 = __shfl_sync(0xffffffffu, wv, k);
            int   sk0 = __shfl_sync(0xffffffffu, s, k);
            float wk1 = __shfl_sync(0xffffffffu, wv, k + 1);
            int   sk1 = __shfl_sync(0xffffffffu, s, k + 1);
            const float* r0 = xh + (size_t)sk0 * 64;
            const float* r1 = xh + (size_t)sk1 * 64;
            a0 = fmaf(wk0, r0[lane], a0);
            a1 = fmaf(wk0, r0[lane + 32], a1);
            b0 = fmaf(wk1, r1[lane], b0);
            b1 = fmaf(wk1, r1[lane + 32], b1);
        }
        if (k < cnt) {
            float wk = __shfl_sync(0xffffffffu, wv, k);
            int   sk = __shfl_sync(0xffffffffu, s, k);
            const float* r = xh + (size_t)sk * 64;
            a0 = fmaf(wk, r[lane], a0);
            a1 = fmaf(wk, r[lane + 32], a1);
        }
    }
#pragma unroll
    for (int o = 16; o; o >>= 1) zpart += __shfl_xor_sync(0xffffffffu, zpart, o);
    float inv = 1.f / zpart;
    out[(size_t)n * 64 + lane]      = (a0 + b0) * inv + bias[lane];
    out[(size_t)n * 64 + lane + 32] = (a1 + b1) * inv + bias[lane + 32];
}

// ---------------- host ----------------
extern "C" void kernel_launch(void* const* d_in, const int* in_sizes, int n_in,
                              void* d_out, int out_size) {
    const float* x     = (const float*)d_in[0];
    const int*   ei    = (const int*)  d_in[1];
    const float* w1    = (const float*)d_in[2];
    const float* b1    = (const float*)d_in[3];
    const float* w2    = (const float*)d_in[4];
    const float* b2    = (const float*)d_in[5];
    const float* g1w   = (const float*)d_in[6];
    const float* g1as  = (const float*)d_in[7];
    const float* g1ad  = (const float*)d_in[8];
    const float* g1b   = (const float*)d_in[9];
    const float* g2w   = (const float*)d_in[10];
    const float* g2as  = (const float*)d_in[11];
    const float* g2ad  = (const float*)d_in[12];
    const float* g2b   = (const float*)d_in[13];
    const float* g3w   = (const float*)d_in[14];
    const float* g3as  = (const float*)d_in[15];
    const float* g3ad  = (const float*)d_in[16];
    const float* g3b   = (const float*)d_in[17];

    int E = in_sizes[1] / 2;
    if (E > EMAX) E = EMAX;
    const int* srcp = ei;
    const int* dstp = ei + E;

    float *xh, *ssrc, *sdst;
    int *deg, *cur;
    __nv_bfloat16 *Phi, *Plo, *Qhi, *Qlo, *whi, *wlo;
    cudaGetSymbolAddress((void**)&xh,   g_xh);
    cudaGetSymbolAddress((void**)&ssrc, g_ssrc);
    cudaGetSymbolAddress((void**)&sdst, g_sdst);
    cudaGetSymbolAddress((void**)&deg,  g_deg);
    cudaGetSymbolAddress((void**)&cur,  g_cur);
    cudaGetSymbolAddress((void**)&Phi,  g_Phi);
    cudaGetSymbolAddress((void**)&Plo,  g_Plo);
    cudaGetSymbolAddress((void**)&Qhi,  g_Qhi);
    cudaGetSymbolAddress((void**)&Qlo,  g_Qlo);
    cudaGetSymbolAddress((void**)&whi,  g_whi);
    cudaGetSymbolAddress((void**)&wlo,  g_wlo);

    const int OW1 = 0, OW2 = 32768, OG1 = 49152, OG2 = 81920, OG3 = 114688;
    const int GY = (NN + 127) / 128;   // 391

    // ---- launches 1-5: memsets + first splits (launch #6 = big tgemm for ncu) ----
    cudaMemsetAsync(deg, 0, NN * sizeof(int));
    cudaMemsetAsync(cur, 0, NN * sizeof(int));
    {
        int n4 = NN * 256 / 4;
        split4_kernel<<<(n4 + 255) / 256, 256>>>((const float4*)x, (__nv_bfloat162*)Phi, (__nv_bfloat162*)Plo, n4);
        split4_kernel<<<(32768/4 + 255) / 256, 256>>>((const float4*)w1,  (__nv_bfloat162*)(whi + OW1), (__nv_bfloat162*)(wlo + OW1), 32768/4);
        split4_kernel<<<(16384/4 + 255) / 256, 256>>>((const float4*)w2,  (__nv_bfloat162*)(whi + OW2), (__nv_bfloat162*)(wlo + OW2), 16384/4);
    }

    // ---- launch #6: MLP GEMM 1 (profiled) ----
    tgemm_kernel<<<dim3(1, GY), 256>>>(Phi, Plo, whi + OW1, wlo + OW1, b1, nullptr, Qhi, Qlo,
                                       nullptr, nullptr, nullptr, nullptr, 0, NN, 256, 128, 1);

    // ---- remaining splits + CSR build ----
    split4_kernel<<<(32768/4 + 255) / 256, 256>>>((const float4*)g1w, (__nv_bfloat162*)(whi + OG1), (__nv_bfloat162*)(wlo + OG1), 32768/4);
    split4_kernel<<<(32768/4 + 255) / 256, 256>>>((const float4*)g2w, (__nv_bfloat162*)(whi + OG2), (__nv_bfloat162*)(wlo + OG2), 32768/4);
    split4_kernel<<<(4096/4 + 255) / 256, 256>>>((const float4*)g3w,  (__nv_bfloat162*)(whi + OG3), (__nv_bfloat162*)(wlo + OG3), 4096/4);
    deg_kernel<<<(E + 255) / 256, 256>>>(dstp, E);
    scan_kernel<<<1, 1024>>>(NN);
    scatter_kernel<<<(E + 255) / 256, 256>>>(srcp, dstp, E);

    // ---- MLP GEMM 2 ----
    tgemm_kernel<<<dim3(1, GY), 256>>>(Qhi, Qlo, whi + OW2, wlo + OW2, b2, nullptr, Phi, Plo,
                                       nullptr, nullptr, nullptr, nullptr, 0, NN, 128, 128, 1);

    // ---- GAT 1 (scores fused in GEMM; agg fused with bias+elu+split) ----
    tgemm_kernel<<<dim3(2, GY), 256>>>(Phi, Plo, whi + OG1, wlo + OG1, nullptr, xh, nullptr, nullptr,
                                       g1as, g1ad, ssrc, sdst, 4, NN, 128, 256, 0);
    agg1_kernel<<<(NN * 4 * 32 + 255) / 256, 256>>>(xh, ssrc, sdst, g1b, Qhi, Qlo);

    // ---- GAT 2 ----
    tgemm_kernel<<<dim3(1, GY), 256>>>(Qhi, Qlo, whi + OG2, wlo + OG2, nullptr, xh, nullptr, nullptr,
                                       g2as, g2ad, ssrc, sdst, 2, NN, 256, 128, 0);
    agg2_kernel<<<(NN * 32 + 255) / 256, 256>>>(xh, ssrc, sdst, g2b, Phi, Plo);

    // ---- GAT 3 ----
    tgemm_kernel<<<dim3(1, GY), 256>>>(Phi, Plo, whi + OG3, wlo + OG3, nullptr, xh, nullptr, nullptr,
                                       g3as, g3ad, ssrc, sdst, 1, NN, 64, 64, 0);
    agg3_kernel<<<(NN * 32 + 255) / 256, 256>>>(xh, ssrc, sdst, g3b, (float*)d_out);
}